// round 5
// baseline (speedup 1.0000x reference)
#include <cuda_runtime.h>
#include <cuda_bf16.h>
#include <cstdint>

// ============================================================================
// ContrastiveLoss, N=16384, D=128, T=0.5, labels in [0,64).
//   K0z: zero histogram + label dtype sniff (int32 vs int64)
//   K0 : fp32->bf16 (A pre-scaled by 2*log2 e), histogram, self-dot exp2
//   K1 : mma.sync m16n8k16 bf16, A register-resident, double-buffered cp.async
//        B chunks; DOUBLE-BUFFERED ACCUMULATORS: MMA of chunk c interleaved
//        at source level with the ex2/label epilogue of chunk c-1 so the
//        tensor and MUFU pipes overlap instead of phase-serializing.
//   K2 : per-row loss from g_pos/g_all/g_self + block reduce
//   K3 : final reduce -> d_out[0]
// ============================================================================

#define NMAX 16384
#define DIM  128
#define BM   128
#define BN   64
#define LDSB 136                // padded bf16 row stride (272 B)
#define EXP_SCALE 2.8853900817779268f   // 2 * log2(e)

__device__ __nv_bfloat16 g_As[NMAX * DIM];   // scaled copy (A operand)
__device__ __nv_bfloat16 g_Bb[NMAX * DIM];   // unscaled copy (B operand)
__device__ unsigned char g_lab[NMAX];
__device__ int           g_cnt[64];
__device__ int           g_is64;
__device__ float         g_self[NMAX];
__device__ float         g_pos[NMAX];
__device__ float         g_all[NMAX];
__device__ float         g_bsum[256];
__device__ int           g_bcnt[256];

// ---------------------------------------------------------------- helpers ---
__device__ __forceinline__ unsigned smem_u32(const void* p) {
    return (unsigned)__cvta_generic_to_shared(p);
}
__device__ __forceinline__ void cp16(unsigned dst, const void* src) {
    asm volatile("cp.async.cg.shared.global [%0], [%1], 16;\n" :: "r"(dst), "l"(src));
}
__device__ __forceinline__ void cp_commit() {
    asm volatile("cp.async.commit_group;\n");
}
template <int N>
__device__ __forceinline__ void cp_wait() {
    asm volatile("cp.async.wait_group %0;\n" :: "n"(N));
}
__device__ __forceinline__ void ldm4(unsigned addr, unsigned& r0, unsigned& r1,
                                     unsigned& r2, unsigned& r3) {
    asm volatile("ldmatrix.sync.aligned.m8n8.x4.shared.b16 {%0,%1,%2,%3}, [%4];\n"
                 : "=r"(r0), "=r"(r1), "=r"(r2), "=r"(r3) : "r"(addr));
}
__device__ __forceinline__ void mma16816(float& c0, float& c1, float& c2, float& c3,
                                         unsigned a0, unsigned a1, unsigned a2, unsigned a3,
                                         unsigned b0, unsigned b1) {
    asm volatile("mma.sync.aligned.m16n8k16.row.col.f32.bf16.bf16.f32 "
                 "{%0,%1,%2,%3},{%4,%5,%6,%7},{%8,%9},{%0,%1,%2,%3};\n"
                 : "+f"(c0), "+f"(c1), "+f"(c2), "+f"(c3)
                 : "r"(a0), "r"(a1), "r"(a2), "r"(a3), "r"(b0), "r"(b1));
}
__device__ __forceinline__ float ex2f(float x) {
    float y;
    asm("ex2.approx.f32 %0, %1;\n" : "=f"(y) : "f"(x));
    return y;
}

// ------------------------------------------------------------------ K0z -----
__global__ void k_zero(const int* __restrict__ labw) {
    if (threadIdx.x == 0) {
        int odd_or = 0;
        for (int i = 0; i < 64; ++i) odd_or |= labw[2 * i + 1];
        g_is64 = (odd_or == 0) ? 1 : 0;
    }
    if (threadIdx.x < 64) g_cnt[threadIdx.x] = 0;
}

// ------------------------------------------------------------------ K0 ------
__global__ void k_convert(const float* __restrict__ emb,
                          const void* __restrict__ lab, int n) {
    int row = blockIdx.x * blockDim.x + threadIdx.x;
    if (row >= n) return;
    const float4* src = (const float4*)(emb + (size_t)row * DIM);
    __nv_bfloat162* dA = (__nv_bfloat162*)(g_As + (size_t)row * DIM);
    __nv_bfloat162* dB = (__nv_bfloat162*)(g_Bb + (size_t)row * DIM);
    float s = 0.f;
#pragma unroll
    for (int i = 0; i < DIM / 4; ++i) {
        float4 v = src[i];
        __nv_bfloat162 a01 = __floats2bfloat162_rn(v.x * EXP_SCALE, v.y * EXP_SCALE);
        __nv_bfloat162 a23 = __floats2bfloat162_rn(v.z * EXP_SCALE, v.w * EXP_SCALE);
        __nv_bfloat162 b01 = __floats2bfloat162_rn(v.x, v.y);
        __nv_bfloat162 b23 = __floats2bfloat162_rn(v.z, v.w);
        dA[2 * i] = a01; dA[2 * i + 1] = a23;
        dB[2 * i] = b01; dB[2 * i + 1] = b23;
        s += __bfloat162float(a01.x) * __bfloat162float(b01.x)
           + __bfloat162float(a01.y) * __bfloat162float(b01.y)
           + __bfloat162float(a23.x) * __bfloat162float(b23.x)
           + __bfloat162float(a23.y) * __bfloat162float(b23.y);
    }
    g_self[row] = ex2f(s);                    // exp of the diagonal sim term
    int lb = g_is64 ? (int)((const long long*)lab)[row]
                    : ((const int*)lab)[row];
    g_lab[row] = (unsigned char)lb;
    atomicAdd(&g_cnt[lb & 63], 1);
}

// ------------------------------------------------------------------ K1 ------
__global__ __launch_bounds__(256, 1) void k_main(int n) {
    __shared__ __align__(16) __nv_bfloat16 sB[2][BN * LDSB];
    __shared__ __align__(16) unsigned char sLab[2][BN];

    const int tid  = threadIdx.x;
    const int lane = tid & 31;
    const int wid  = tid >> 5;        // 0..7, owns rows [wid*16, wid*16+16)
    const int g    = lane >> 2;       // 0..7
    const int t    = lane & 3;        // 0..3
    const int nch  = n / BN;

    // ---- stage A tile (128 rows) into the two B buffers, pull to registers
    {
        const __nv_bfloat16* gA = g_As + (size_t)(blockIdx.x * BM) * DIM;
#pragma unroll
        for (int k = 0; k < 8; ++k) {
            int s = tid + k * 256;            // 0..2047 segments of 16 B
            int row = s >> 4, seg = s & 15;
            int half = row >> 6, lrow = row & 63;
            cp16(smem_u32(&sB[half][lrow * LDSB + seg * 8]), gA + row * DIM + seg * 8);
        }
        cp_commit();
        cp_wait<0>();
        __syncthreads();
    }

    unsigned af[8][4];                 // A fragments for the full K=128
    {
        int half   = wid >> 2;
        int lrbase = (wid & 3) * 16;
        int arow   = lrbase + (lane & 15);
        int acolo  = (lane >> 4) * 8;
#pragma unroll
        for (int kt = 0; kt < 8; ++kt) {
            unsigned addr = smem_u32(&sB[half][arow * LDSB + kt * 16 + acolo]);
            ldm4(addr, af[kt][0], af[kt][1], af[kt][2], af[kt][3]);
        }
    }
    __syncthreads();

    const int rb = blockIdx.x * BM + wid * 16;
    const unsigned lr0 = g_lab[rb + g];
    const unsigned lr1 = g_lab[rb + g + 8];

    float all0 = 0.f, all1 = 0.f, pos0 = 0.f, pos1 = 0.f;

    const int brow_off = (lane & 7) + ((lane >> 4) << 3);
    const int bcol_off = ((lane >> 3) & 1) * 8;

    auto load_chunk = [&](int c, int buf) {
        const __nv_bfloat16* gB = g_Bb + (size_t)(c * BN) * DIM;
#pragma unroll
        for (int k = 0; k < 4; ++k) {
            int s = tid + k * 256;            // 0..1023 segments of 16 B
            int row = s >> 4, seg = s & 15;
            cp16(smem_u32(&sB[buf][row * LDSB + seg * 8]), gB + row * DIM + seg * 8);
        }
        if (tid < 4)
            cp16(smem_u32(&sLab[buf][tid * 16]), g_lab + c * BN + tid * 16);
        cp_commit();
    };

    // double-buffered accumulators + label registers (ping-pong on c&1)
    float acc[2][8][4];
#pragma unroll
    for (int p = 0; p < 2; ++p)
#pragma unroll
        for (int i = 0; i < 8; ++i)
#pragma unroll
            for (int j = 0; j < 4; ++j) acc[p][i][j] = 0.f;
    unsigned short labr[2][8];

    load_chunk(0, 0);
    if (nch > 1) load_chunk(1, 1);

    // ---- peeled iteration 0: MMA only (no previous chunk to epilogue)
    {
        cp_wait<1>();
        __syncthreads();
#pragma unroll
        for (int kt = 0; kt < 8; ++kt)
            labr[0][kt] = *(const unsigned short*)&sLab[0][kt * 8 + 2 * t];
#pragma unroll
        for (int kt = 0; kt < 8; ++kt) {
#pragma unroll
            for (int np = 0; np < 4; ++np) {
                unsigned b0, b1, b2, b3;
                unsigned addr = smem_u32(
                    &sB[0][(np * 16 + brow_off) * LDSB + kt * 16 + bcol_off]);
                ldm4(addr, b0, b1, b2, b3);
                mma16816(acc[0][2 * np][0], acc[0][2 * np][1],
                         acc[0][2 * np][2], acc[0][2 * np][3],
                         af[kt][0], af[kt][1], af[kt][2], af[kt][3], b0, b1);
                mma16816(acc[0][2 * np + 1][0], acc[0][2 * np + 1][1],
                         acc[0][2 * np + 1][2], acc[0][2 * np + 1][3],
                         af[kt][0], af[kt][1], af[kt][2], af[kt][3], b2, b3);
            }
        }
        __syncthreads();
        if (2 < nch) load_chunk(2, 0);
    }

    // ---- steady state: MMA(c) interleaved with epilogue(c-1)
    for (int c = 1; c < nch; ++c) {
        const int buf = c & 1, prv = buf ^ 1;
        if (c + 1 == nch) cp_wait<0>(); else cp_wait<1>();
        __syncthreads();
#pragma unroll
        for (int kt = 0; kt < 8; ++kt)
            labr[buf][kt] = *(const unsigned short*)&sLab[buf][kt * 8 + 2 * t];

#pragma unroll
        for (int kt = 0; kt < 8; ++kt) {
            // MMA slice of chunk c (tensor pipe)
#pragma unroll
            for (int np = 0; np < 4; ++np) {
                unsigned b0, b1, b2, b3;
                unsigned addr = smem_u32(
                    &sB[buf][(np * 16 + brow_off) * LDSB + kt * 16 + bcol_off]);
                ldm4(addr, b0, b1, b2, b3);
                mma16816(acc[buf][2 * np][0], acc[buf][2 * np][1],
                         acc[buf][2 * np][2], acc[buf][2 * np][3],
                         af[kt][0], af[kt][1], af[kt][2], af[kt][3], b0, b1);
                mma16816(acc[buf][2 * np + 1][0], acc[buf][2 * np + 1][1],
                         acc[buf][2 * np + 1][2], acc[buf][2 * np + 1][3],
                         af[kt][0], af[kt][1], af[kt][2], af[kt][3], b2, b3);
            }
            // epilogue slice of chunk c-1, n-tile kt (MUFU/ALU pipes)
            {
                unsigned short pr = labr[prv][kt];
                unsigned l0 = pr & 0xFFu, l1 = pr >> 8;
                float e00 = ex2f(acc[prv][kt][0]);
                float e01 = ex2f(acc[prv][kt][1]);
                float e10 = ex2f(acc[prv][kt][2]);
                float e11 = ex2f(acc[prv][kt][3]);
                all0 += e00 + e01;
                all1 += e10 + e11;
                if (l0 == lr0) pos0 += e00;
                if (l1 == lr0) pos0 += e01;
                if (l0 == lr1) pos1 += e10;
                if (l1 == lr1) pos1 += e11;
                acc[prv][kt][0] = 0.f; acc[prv][kt][1] = 0.f;
                acc[prv][kt][2] = 0.f; acc[prv][kt][3] = 0.f;
            }
        }
        __syncthreads();
        if (c + 2 < nch) load_chunk(c + 2, buf);
    }

    // ---- tail epilogue for chunk nch-1
    {
        const int prv = (nch - 1) & 1;
#pragma unroll
        for (int kt = 0; kt < 8; ++kt) {
            unsigned short pr = labr[prv][kt];
            unsigned l0 = pr & 0xFFu, l1 = pr >> 8;
            float e00 = ex2f(acc[prv][kt][0]);
            float e01 = ex2f(acc[prv][kt][1]);
            float e10 = ex2f(acc[prv][kt][2]);
            float e11 = ex2f(acc[prv][kt][3]);
            all0 += e00 + e01;
            all1 += e10 + e11;
            if (l0 == lr0) pos0 += e00;
            if (l1 == lr0) pos0 += e01;
            if (l0 == lr1) pos1 += e10;
            if (l1 == lr1) pos1 += e11;
        }
    }

    // reduce across the 4 lanes of each quad (same g -> same rows)
#pragma unroll
    for (int off = 1; off <= 2; off <<= 1) {
        all0 += __shfl_xor_sync(0xffffffffu, all0, off);
        all1 += __shfl_xor_sync(0xffffffffu, all1, off);
        pos0 += __shfl_xor_sync(0xffffffffu, pos0, off);
        pos1 += __shfl_xor_sync(0xffffffffu, pos1, off);
    }
    if (t == 0) {
        g_all[rb + g] = all0;     g_pos[rb + g] = pos0;
        g_all[rb + g + 8] = all1; g_pos[rb + g + 8] = pos1;
    }
}

// ------------------------------------------------------------------ K2 ------
__global__ void k_rowloss(int n) {
    int row = blockIdx.x * blockDim.x + threadIdx.x;
    float li = 0.f;
    int v = 0;
    if (row < n) {
        float es  = g_self[row];
        float pos = g_pos[row] - es;
        float all = g_all[row] - es;
        v = (g_cnt[g_lab[row]] > 1) ? 1 : 0;
        if (v) li = logf(all) - logf(pos);
    }
    __shared__ float ssum[256];
    __shared__ int   scnt[256];
    ssum[threadIdx.x] = li;
    scnt[threadIdx.x] = v;
    __syncthreads();
    for (int o = 128; o > 0; o >>= 1) {
        if (threadIdx.x < o) {
            ssum[threadIdx.x] += ssum[threadIdx.x + o];
            scnt[threadIdx.x] += scnt[threadIdx.x + o];
        }
        __syncthreads();
    }
    if (threadIdx.x == 0) {
        g_bsum[blockIdx.x] = ssum[0];
        g_bcnt[blockIdx.x] = scnt[0];
    }
}

// ------------------------------------------------------------------ K3 ------
__global__ void k_final(float* out, int nb) {
    float s = 0.f;
    int c = 0;
    for (int i = threadIdx.x; i < nb; i += 32) {
        s += g_bsum[i];
        c += g_bcnt[i];
    }
#pragma unroll
    for (int o = 16; o > 0; o >>= 1) {
        s += __shfl_xor_sync(0xffffffffu, s, o);
        c += __shfl_xor_sync(0xffffffffu, c, o);
    }
    if (threadIdx.x == 0) out[0] = (c > 0) ? (s / (float)c) : 0.f;
}

// ----------------------------------------------------------------- launch ---
extern "C" void kernel_launch(void* const* d_in, const int* in_sizes, int n_in,
                              void* d_out, int out_size) {
    const float* emb = (const float*)d_in[0];
    const void*  lab = d_in[1];
    int n = in_sizes[1];                       // 16384

    k_zero<<<1, 64>>>((const int*)lab);
    k_convert<<<(n + 255) / 256, 256>>>(emb, lab, n);
    k_main<<<n / BM, 256>>>(n);
    int nb2 = (n + 255) / 256;                 // 64
    k_rowloss<<<nb2, 256>>>(n);
    k_final<<<1, 32>>>((float*)d_out, nb2);
}

// round 8
// speedup vs baseline: 1.9820x; 1.9820x over previous
#include <cuda_runtime.h>
#include <cuda_bf16.h>
#include <cstdint>

// ============================================================================
// ContrastiveLoss, N=16384, D=128, T=0.5, labels in [0,64).
//   K0z: zero histogram + label dtype sniff (int32 vs int64)
//   K0 : fp32->bf16 (A pre-scaled by 2*log2 e), histogram, self-dot exp2
//   K1 : mma.sync m16n8k16 bf16, A register-resident, double-buffered cp.async
//        B chunks; accumulator double-buffering with COMPILE-TIME-CONSTANT
//        indices (two named arrays, pair-unrolled loop) so MMA of chunk c
//        interleaves with the ex2/label epilogue of chunk c-1 without local
//        memory spills (the R5 failure: runtime-indexed acc[2][..] -> LDL/STL).
//   K2 : per-row loss from g_pos/g_all/g_self + block reduce
//   K3 : final reduce -> d_out[0]
// ============================================================================

#define NMAX 16384
#define DIM  128
#define BM   128
#define BN   64
#define LDSB 136                // padded bf16 row stride (272 B)
#define EXP_SCALE 2.8853900817779268f   // 2 * log2(e)

__device__ __nv_bfloat16 g_As[NMAX * DIM];   // scaled copy (A operand)
__device__ __nv_bfloat16 g_Bb[NMAX * DIM];   // unscaled copy (B operand)
__device__ unsigned char g_lab[NMAX];
__device__ int           g_cnt[64];
__device__ int           g_is64;
__device__ float         g_self[NMAX];
__device__ float         g_pos[NMAX];
__device__ float         g_all[NMAX];
__device__ float         g_bsum[256];
__device__ int           g_bcnt[256];

// ---------------------------------------------------------------- helpers ---
__device__ __forceinline__ unsigned smem_u32(const void* p) {
    return (unsigned)__cvta_generic_to_shared(p);
}
__device__ __forceinline__ void cp16(unsigned dst, const void* src) {
    asm volatile("cp.async.cg.shared.global [%0], [%1], 16;\n" :: "r"(dst), "l"(src));
}
__device__ __forceinline__ void cp_commit() {
    asm volatile("cp.async.commit_group;\n");
}
template <int N>
__device__ __forceinline__ void cp_wait() {
    asm volatile("cp.async.wait_group %0;\n" :: "n"(N));
}
__device__ __forceinline__ void ldm4(unsigned addr, unsigned& r0, unsigned& r1,
                                     unsigned& r2, unsigned& r3) {
    asm volatile("ldmatrix.sync.aligned.m8n8.x4.shared.b16 {%0,%1,%2,%3}, [%4];\n"
                 : "=r"(r0), "=r"(r1), "=r"(r2), "=r"(r3) : "r"(addr));
}
__device__ __forceinline__ void mma16816(float& c0, float& c1, float& c2, float& c3,
                                         unsigned a0, unsigned a1, unsigned a2, unsigned a3,
                                         unsigned b0, unsigned b1) {
    asm volatile("mma.sync.aligned.m16n8k16.row.col.f32.bf16.bf16.f32 "
                 "{%0,%1,%2,%3},{%4,%5,%6,%7},{%8,%9},{%0,%1,%2,%3};\n"
                 : "+f"(c0), "+f"(c1), "+f"(c2), "+f"(c3)
                 : "r"(a0), "r"(a1), "r"(a2), "r"(a3), "r"(b0), "r"(b1));
}
__device__ __forceinline__ float ex2f(float x) {
    float y;
    asm("ex2.approx.f32 %0, %1;\n" : "=f"(y) : "f"(x));
    return y;
}

// ------------------------------------------------------------------ K0z -----
__global__ void k_zero(const int* __restrict__ labw) {
    if (threadIdx.x == 0) {
        int odd_or = 0;
        for (int i = 0; i < 64; ++i) odd_or |= labw[2 * i + 1];
        g_is64 = (odd_or == 0) ? 1 : 0;
    }
    if (threadIdx.x < 64) g_cnt[threadIdx.x] = 0;
}

// ------------------------------------------------------------------ K0 ------
__global__ void k_convert(const float* __restrict__ emb,
                          const void* __restrict__ lab, int n) {
    int row = blockIdx.x * blockDim.x + threadIdx.x;
    if (row >= n) return;
    const float4* src = (const float4*)(emb + (size_t)row * DIM);
    __nv_bfloat162* dA = (__nv_bfloat162*)(g_As + (size_t)row * DIM);
    __nv_bfloat162* dB = (__nv_bfloat162*)(g_Bb + (size_t)row * DIM);
    float s = 0.f;
#pragma unroll
    for (int i = 0; i < DIM / 4; ++i) {
        float4 v = src[i];
        __nv_bfloat162 a01 = __floats2bfloat162_rn(v.x * EXP_SCALE, v.y * EXP_SCALE);
        __nv_bfloat162 a23 = __floats2bfloat162_rn(v.z * EXP_SCALE, v.w * EXP_SCALE);
        __nv_bfloat162 b01 = __floats2bfloat162_rn(v.x, v.y);
        __nv_bfloat162 b23 = __floats2bfloat162_rn(v.z, v.w);
        dA[2 * i] = a01; dA[2 * i + 1] = a23;
        dB[2 * i] = b01; dB[2 * i + 1] = b23;
        s += __bfloat162float(a01.x) * __bfloat162float(b01.x)
           + __bfloat162float(a01.y) * __bfloat162float(b01.y)
           + __bfloat162float(a23.x) * __bfloat162float(b23.x)
           + __bfloat162float(a23.y) * __bfloat162float(b23.y);
    }
    g_self[row] = ex2f(s);                    // exp of the diagonal sim term
    int lb = g_is64 ? (int)((const long long*)lab)[row]
                    : ((const int*)lab)[row];
    g_lab[row] = (unsigned char)lb;
    atomicAdd(&g_cnt[lb & 63], 1);
}

// ------------------------------------------------------------------ K1 ------
__global__ __launch_bounds__(256, 1) void k_main(int n) {
    __shared__ __align__(16) __nv_bfloat16 sB[2][BN * LDSB];
    __shared__ __align__(16) unsigned char sLab[2][BN];

    const int tid  = threadIdx.x;
    const int lane = tid & 31;
    const int wid  = tid >> 5;        // 0..7, owns rows [wid*16, wid*16+16)
    const int g    = lane >> 2;       // 0..7
    const int t    = lane & 3;        // 0..3
    const int nch  = n / BN;          // 256 (even; n % 128 == 0)

    // ---- stage A tile (128 rows) into the two B buffers, pull to registers
    {
        const __nv_bfloat16* gA = g_As + (size_t)(blockIdx.x * BM) * DIM;
#pragma unroll
        for (int k = 0; k < 8; ++k) {
            int s = tid + k * 256;            // 0..2047 segments of 16 B
            int row = s >> 4, seg = s & 15;
            int half = row >> 6, lrow = row & 63;
            cp16(smem_u32(&sB[half][lrow * LDSB + seg * 8]), gA + row * DIM + seg * 8);
        }
        cp_commit();
        cp_wait<0>();
        __syncthreads();
    }

    unsigned af[8][4];                 // A fragments for the full K=128
    {
        int half   = wid >> 2;
        int lrbase = (wid & 3) * 16;
        int arow   = lrbase + (lane & 15);
        int acolo  = (lane >> 4) * 8;
#pragma unroll
        for (int kt = 0; kt < 8; ++kt) {
            unsigned addr = smem_u32(&sB[half][arow * LDSB + kt * 16 + acolo]);
            ldm4(addr, af[kt][0], af[kt][1], af[kt][2], af[kt][3]);
        }
    }
    __syncthreads();

    const int rb = blockIdx.x * BM + wid * 16;
    const unsigned lr0 = g_lab[rb + g];
    const unsigned lr1 = g_lab[rb + g + 8];

    float all0 = 0.f, all1 = 0.f, pos0 = 0.f, pos1 = 0.f;

    const int brow_off = (lane & 7) + ((lane >> 4) << 3);
    const int bcol_off = ((lane >> 3) & 1) * 8;

    auto load_chunk = [&](int c, int buf) {
        const __nv_bfloat16* gB = g_Bb + (size_t)(c * BN) * DIM;
#pragma unroll
        for (int k = 0; k < 4; ++k) {
            int s = tid + k * 256;            // 0..1023 segments of 16 B
            int row = s >> 4, seg = s & 15;
            cp16(smem_u32(&sB[buf][row * LDSB + seg * 8]), gB + row * DIM + seg * 8);
        }
        if (tid < 4)
            cp16(smem_u32(&sLab[buf][tid * 16]), g_lab + c * BN + tid * 16);
        cp_commit();
    };

    // two NAMED accumulator sets -> constant register indices at every use
    float accA[8][4], accB[8][4];
#pragma unroll
    for (int i = 0; i < 8; ++i)
#pragma unroll
        for (int j = 0; j < 4; ++j) { accA[i][j] = 0.f; accB[i][j] = 0.f; }
    unsigned short labA[8], labB[8];

    // one steady-state step: MMA chunk c into accC (buffer buf = c&1),
    // interleaved with the epilogue of chunk c-1 held in accP/labP.
    auto step = [&](int c, int buf,
                    float (&accC)[8][4], float (&accP)[8][4],
                    unsigned short (&labC)[8], unsigned short (&labP)[8]) {
        if (c + 1 == nch) cp_wait<0>(); else cp_wait<1>();
        __syncthreads();
#pragma unroll
        for (int kt = 0; kt < 8; ++kt)
            labC[kt] = *(const unsigned short*)&sLab[buf][kt * 8 + 2 * t];

#pragma unroll
        for (int kt = 0; kt < 8; ++kt) {
            // MMA slice of chunk c (tensor pipe)
#pragma unroll
            for (int np = 0; np < 4; ++np) {
                unsigned b0, b1, b2, b3;
                unsigned addr = smem_u32(
                    &sB[buf][(np * 16 + brow_off) * LDSB + kt * 16 + bcol_off]);
                ldm4(addr, b0, b1, b2, b3);
                mma16816(accC[2 * np][0], accC[2 * np][1],
                         accC[2 * np][2], accC[2 * np][3],
                         af[kt][0], af[kt][1], af[kt][2], af[kt][3], b0, b1);
                mma16816(accC[2 * np + 1][0], accC[2 * np + 1][1],
                         accC[2 * np + 1][2], accC[2 * np + 1][3],
                         af[kt][0], af[kt][1], af[kt][2], af[kt][3], b2, b3);
            }
            // epilogue slice of chunk c-1, n-tile kt (MUFU/ALU pipes)
            {
                unsigned short pr = labP[kt];
                unsigned l0 = pr & 0xFFu, l1 = pr >> 8;
                float e00 = ex2f(accP[kt][0]);
                float e01 = ex2f(accP[kt][1]);
                float e10 = ex2f(accP[kt][2]);
                float e11 = ex2f(accP[kt][3]);
                all0 += e00 + e01;
                all1 += e10 + e11;
                if (l0 == lr0) pos0 += e00;
                if (l1 == lr0) pos0 += e01;
                if (l0 == lr1) pos1 += e10;
                if (l1 == lr1) pos1 += e11;
                accP[kt][0] = 0.f; accP[kt][1] = 0.f;
                accP[kt][2] = 0.f; accP[kt][3] = 0.f;
            }
        }
        __syncthreads();
        if (c + 2 < nch) load_chunk(c + 2, buf);
    };

    load_chunk(0, 0);
    if (nch > 1) load_chunk(1, 1);

    // ---- peeled iteration 0: MMA only into accA (no previous chunk)
    {
        cp_wait<1>();
        __syncthreads();
#pragma unroll
        for (int kt = 0; kt < 8; ++kt)
            labA[kt] = *(const unsigned short*)&sLab[0][kt * 8 + 2 * t];
#pragma unroll
        for (int kt = 0; kt < 8; ++kt) {
#pragma unroll
            for (int np = 0; np < 4; ++np) {
                unsigned b0, b1, b2, b3;
                unsigned addr = smem_u32(
                    &sB[0][(np * 16 + brow_off) * LDSB + kt * 16 + bcol_off]);
                ldm4(addr, b0, b1, b2, b3);
                mma16816(accA[2 * np][0], accA[2 * np][1],
                         accA[2 * np][2], accA[2 * np][3],
                         af[kt][0], af[kt][1], af[kt][2], af[kt][3], b0, b1);
                mma16816(accA[2 * np + 1][0], accA[2 * np + 1][1],
                         accA[2 * np + 1][2], accA[2 * np + 1][3],
                         af[kt][0], af[kt][1], af[kt][2], af[kt][3], b2, b3);
            }
        }
        __syncthreads();
        if (2 < nch) load_chunk(2, 0);
    }

    // ---- steady state, pair-unrolled so all acc indices are compile-time.
    // nch is even: c = 1..nch-2 in pairs, then single c = nch-1.
    int c = 1;
    for (; c + 1 < nch; c += 2) {
        step(c,     1, accB, accA, labB, labA);
        step(c + 1, 0, accA, accB, labA, labB);
    }
    // final chunk (c == nch-1, odd -> buffer 1, into accB, epilogue of accA)
    step(c, 1, accB, accA, labB, labA);

    // ---- tail epilogue for chunk nch-1 (in accB/labB)
#pragma unroll
    for (int kt = 0; kt < 8; ++kt) {
        unsigned short pr = labB[kt];
        unsigned l0 = pr & 0xFFu, l1 = pr >> 8;
        float e00 = ex2f(accB[kt][0]);
        float e01 = ex2f(accB[kt][1]);
        float e10 = ex2f(accB[kt][2]);
        float e11 = ex2f(accB[kt][3]);
        all0 += e00 + e01;
        all1 += e10 + e11;
        if (l0 == lr0) pos0 += e00;
        if (l1 == lr0) pos0 += e01;
        if (l0 == lr1) pos1 += e10;
        if (l1 == lr1) pos1 += e11;
    }

    // reduce across the 4 lanes of each quad (same g -> same rows)
#pragma unroll
    for (int off = 1; off <= 2; off <<= 1) {
        all0 += __shfl_xor_sync(0xffffffffu, all0, off);
        all1 += __shfl_xor_sync(0xffffffffu, all1, off);
        pos0 += __shfl_xor_sync(0xffffffffu, pos0, off);
        pos1 += __shfl_xor_sync(0xffffffffu, pos1, off);
    }
    if (t == 0) {
        g_all[rb + g] = all0;     g_pos[rb + g] = pos0;
        g_all[rb + g + 8] = all1; g_pos[rb + g + 8] = pos1;
    }
}

// ------------------------------------------------------------------ K2 ------
__global__ void k_rowloss(int n) {
    int row = blockIdx.x * blockDim.x + threadIdx.x;
    float li = 0.f;
    int v = 0;
    if (row < n) {
        float es  = g_self[row];
        float pos = g_pos[row] - es;
        float all = g_all[row] - es;
        v = (g_cnt[g_lab[row]] > 1) ? 1 : 0;
        if (v) li = logf(all) - logf(pos);
    }
    __shared__ float ssum[256];
    __shared__ int   scnt[256];
    ssum[threadIdx.x] = li;
    scnt[threadIdx.x] = v;
    __syncthreads();
    for (int o = 128; o > 0; o >>= 1) {
        if (threadIdx.x < o) {
            ssum[threadIdx.x] += ssum[threadIdx.x + o];
            scnt[threadIdx.x] += scnt[threadIdx.x + o];
        }
        __syncthreads();
    }
    if (threadIdx.x == 0) {
        g_bsum[blockIdx.x] = ssum[0];
        g_bcnt[blockIdx.x] = scnt[0];
    }
}

// ------------------------------------------------------------------ K3 ------
__global__ void k_final(float* out, int nb) {
    float s = 0.f;
    int c = 0;
    for (int i = threadIdx.x; i < nb; i += 32) {
        s += g_bsum[i];
        c += g_bcnt[i];
    }
#pragma unroll
    for (int o = 16; o > 0; o >>= 1) {
        s += __shfl_xor_sync(0xffffffffu, s, o);
        c += __shfl_xor_sync(0xffffffffu, c, o);
    }
    if (threadIdx.x == 0) out[0] = (c > 0) ? (s / (float)c) : 0.f;
}

// ----------------------------------------------------------------- launch ---
extern "C" void kernel_launch(void* const* d_in, const int* in_sizes, int n_in,
                              void* d_out, int out_size) {
    const float* emb = (const float*)d_in[0];
    const void*  lab = d_in[1];
    int n = in_sizes[1];                       // 16384

    k_zero<<<1, 64>>>((const int*)lab);
    k_convert<<<(n + 255) / 256, 256>>>(emb, lab, n);
    k_main<<<n / BM, 256>>>(n);
    int nb2 = (n + 255) / 256;                 // 64
    k_rowloss<<<nb2, 256>>>(n);
    k_final<<<1, 32>>>((float*)d_out, nb2);
}

// round 10
// speedup vs baseline: 2.0368x; 1.0277x over previous
#include <cuda_runtime.h>
#include <cuda_bf16.h>
#include <cstdint>

// ============================================================================
// ContrastiveLoss, N=16384, D=128, T=0.5, labels in [0,64).
// R9: SYMMETRY — compute only unordered 128x128 block pairs (8256 instead of
// 16384 tiles of 128x128): each exp value feeds row sums of block I and
// column sums of block J (label mask is symmetric). Halves the tensor work,
// which R8 showed is the binding pipe (legacy HMMA ~512 MAC/cyc/SM).
//   K0z: zero histogram + label dtype sniff
//   K0 : fp32->bf16 (A pre-scaled by 2*log2 e), self-dot exp2, zero g_all/g_pos
//   K1 : persistent 152 CTAs, grid-stride over pairs, double-buffered cp.async,
//        mma.sync bf16, row sums + (off-diagonal) column sums via butterfly,
//        float atomicAdd accumulation; 2nd MMA half interleaved with 1st
//        half's epilogue.
//   K2 : per-row loss (subtract self) + block reduce;  K3: final reduce
// ============================================================================

#define NMAX 16384
#define DIM  128
#define LDSB 136                 // padded bf16 row stride (272 B)
#define EXP_SCALE 2.8853900817779268f   // 2 * log2(e)
#define GRID_MAIN 152
#define ABYTES (128 * LDSB * 2)  // one 128-row bf16 tile buffer = 34816 B
#define SMEM_TOTAL (4 * ABYTES + 256)

__device__ __nv_bfloat16 g_As[NMAX * DIM];   // scaled copy (A operand)
__device__ __nv_bfloat16 g_Bb[NMAX * DIM];   // unscaled copy (B operand)
__device__ unsigned char g_lab[NMAX];
__device__ int           g_cnt[64];
__device__ int           g_is64;
__device__ float         g_self[NMAX];
__device__ float         g_pos[NMAX];
__device__ float         g_all[NMAX];
__device__ float         g_bsum[256];
__device__ int           g_bcnt[256];

// ---------------------------------------------------------------- helpers ---
__device__ __forceinline__ unsigned smem_u32(const void* p) {
    return (unsigned)__cvta_generic_to_shared(p);
}
__device__ __forceinline__ void cp16(unsigned dst, const void* src) {
    asm volatile("cp.async.cg.shared.global [%0], [%1], 16;\n" :: "r"(dst), "l"(src));
}
__device__ __forceinline__ void cp_commit() {
    asm volatile("cp.async.commit_group;\n");
}
template <int N>
__device__ __forceinline__ void cp_wait() {
    asm volatile("cp.async.wait_group %0;\n" :: "n"(N));
}
__device__ __forceinline__ void ldm4(unsigned addr, unsigned& r0, unsigned& r1,
                                     unsigned& r2, unsigned& r3) {
    asm volatile("ldmatrix.sync.aligned.m8n8.x4.shared.b16 {%0,%1,%2,%3}, [%4];\n"
                 : "=r"(r0), "=r"(r1), "=r"(r2), "=r"(r3) : "r"(addr));
}
__device__ __forceinline__ void mma16816(float& c0, float& c1, float& c2, float& c3,
                                         unsigned a0, unsigned a1, unsigned a2, unsigned a3,
                                         unsigned b0, unsigned b1) {
    asm volatile("mma.sync.aligned.m16n8k16.row.col.f32.bf16.bf16.f32 "
                 "{%0,%1,%2,%3},{%4,%5,%6,%7},{%8,%9},{%0,%1,%2,%3};\n"
                 : "+f"(c0), "+f"(c1), "+f"(c2), "+f"(c3)
                 : "r"(a0), "r"(a1), "r"(a2), "r"(a3), "r"(b0), "r"(b1));
}
__device__ __forceinline__ float ex2f(float x) {
    float y;
    asm("ex2.approx.f32 %0, %1;\n" : "=f"(y) : "f"(x));
    return y;
}

// ------------------------------------------------------------------ K0z -----
__global__ void k_zero(const int* __restrict__ labw) {
    if (threadIdx.x == 0) {
        int odd_or = 0;
        for (int i = 0; i < 64; ++i) odd_or |= labw[2 * i + 1];
        g_is64 = (odd_or == 0) ? 1 : 0;
    }
    if (threadIdx.x < 64) g_cnt[threadIdx.x] = 0;
}

// ------------------------------------------------------------------ K0 ------
__global__ void k_convert(const float* __restrict__ emb,
                          const void* __restrict__ lab, int n) {
    int row = blockIdx.x * blockDim.x + threadIdx.x;
    if (row >= n) return;
    const float4* src = (const float4*)(emb + (size_t)row * DIM);
    __nv_bfloat162* dA = (__nv_bfloat162*)(g_As + (size_t)row * DIM);
    __nv_bfloat162* dB = (__nv_bfloat162*)(g_Bb + (size_t)row * DIM);
    float s = 0.f;
#pragma unroll
    for (int i = 0; i < DIM / 4; ++i) {
        float4 v = src[i];
        __nv_bfloat162 a01 = __floats2bfloat162_rn(v.x * EXP_SCALE, v.y * EXP_SCALE);
        __nv_bfloat162 a23 = __floats2bfloat162_rn(v.z * EXP_SCALE, v.w * EXP_SCALE);
        __nv_bfloat162 b01 = __floats2bfloat162_rn(v.x, v.y);
        __nv_bfloat162 b23 = __floats2bfloat162_rn(v.z, v.w);
        dA[2 * i] = a01; dA[2 * i + 1] = a23;
        dB[2 * i] = b01; dB[2 * i + 1] = b23;
        s += __bfloat162float(a01.x) * __bfloat162float(b01.x)
           + __bfloat162float(a01.y) * __bfloat162float(b01.y)
           + __bfloat162float(a23.x) * __bfloat162float(b23.x)
           + __bfloat162float(a23.y) * __bfloat162float(b23.y);
    }
    g_self[row] = ex2f(s);
    g_all[row]  = 0.f;                 // zero atomic accumulators every call
    g_pos[row]  = 0.f;
    int lb = g_is64 ? (int)((const long long*)lab)[row]
                    : ((const int*)lab)[row];
    g_lab[row] = (unsigned char)lb;
    atomicAdd(&g_cnt[lb & 63], 1);
}

// ------------------------------------------------------------------ K1 ------
__global__ __launch_bounds__(256, 1) void k_main(int n) {
    extern __shared__ char smem[];
    // layout: [A buf0][A buf1][B buf0][B buf1][labJ buf0 128B][labJ buf1 128B]

    const int tid  = threadIdx.x;
    const int lane = tid & 31;
    const int wid  = tid >> 5;
    const int g    = lane >> 2;
    const int t    = lane & 3;

    const int nb    = n >> 7;               // 128 blocks of 128 rows
    const int halfP = nb * (nb >> 1);
    const int NP    = nb * (nb + 1) / 2;    // 8256 unordered pairs

    auto decode = [&](int p, int& bi, int& bj, int& off) {
        if (p < halfP) { off = p / nb; bi = p - off * nb; }
        else           { off = nb >> 1; bi = p - halfP; }
        bj = bi + off; if (bj >= nb) bj -= nb;
    };

    auto load_pair = [&](int p, int buf) {
        int bi, bj, off; decode(p, bi, bj, off);
        __nv_bfloat16* A = (__nv_bfloat16*)(smem + (size_t)buf * ABYTES);
        __nv_bfloat16* B = (__nv_bfloat16*)(smem + (size_t)(2 + buf) * ABYTES);
        const __nv_bfloat16* gA = g_As + (size_t)bi * 128 * DIM;
        const __nv_bfloat16* gB = g_Bb + (size_t)bj * 128 * DIM;
#pragma unroll
        for (int k = 0; k < 8; ++k) {
            int s = tid + k * 256;           // 2048 segments of 16 B each array
            int row = s >> 4, seg = s & 15;
            cp16(smem_u32(&A[row * LDSB + seg * 8]), gA + row * DIM + seg * 8);
            cp16(smem_u32(&B[row * LDSB + seg * 8]), gB + row * DIM + seg * 8);
        }
        if (tid < 8)
            cp16(smem_u32(smem + 4 * ABYTES + buf * 128 + tid * 16),
                 g_lab + bj * 128 + tid * 16);
        cp_commit();
    };

    const int brow = (lane & 7) + ((lane >> 4) << 3);
    const int bcol = ((lane >> 3) & 1) * 8;

    int p  = blockIdx.x;
    if (p < NP) load_pair(p, 0);

    int it = 0;
    for (; p < NP; p += GRID_MAIN, ++it) {
        const int buf = it & 1;
        int bi, bj, off; decode(p, bi, bj, off);

        cp_wait<0>();
        __syncthreads();                     // all threads done with buf^1's pair
        if (p + GRID_MAIN < NP) load_pair(p + GRID_MAIN, buf ^ 1);

        __nv_bfloat16* A = (__nv_bfloat16*)(smem + (size_t)buf * ABYTES);
        __nv_bfloat16* B = (__nv_bfloat16*)(smem + (size_t)(2 + buf) * ABYTES);
        unsigned char* LJ = (unsigned char*)(smem + 4 * ABYTES + buf * 128);

        const int rI = bi * 128 + wid * 16;
        const unsigned lr0 = g_lab[rI + g];
        const unsigned lr1 = g_lab[rI + g + 8];

        // A fragments for this pair
        unsigned af[8][4];
        {
            int arow = wid * 16 + (lane & 15);
            int acol = (lane >> 4) * 8;
#pragma unroll
            for (int kt = 0; kt < 8; ++kt)
                ldm4(smem_u32(&A[arow * LDSB + kt * 16 + acol]),
                     af[kt][0], af[kt][1], af[kt][2], af[kt][3]);
        }

        float acc[16][4];
#pragma unroll
        for (int i = 0; i < 16; ++i)
#pragma unroll
            for (int j = 0; j < 4; ++j) acc[i][j] = 0.f;

        float ra0 = 0.f, ra1 = 0.f, rp0 = 0.f, rp1 = 0.f;

        auto mma_np = [&](int np) {
#pragma unroll
            for (int kt = 0; kt < 8; ++kt) {
                unsigned b0, b1, b2, b3;
                ldm4(smem_u32(&B[(np * 16 + brow) * LDSB + kt * 16 + bcol]),
                     b0, b1, b2, b3);
                mma16816(acc[2 * np][0], acc[2 * np][1],
                         acc[2 * np][2], acc[2 * np][3],
                         af[kt][0], af[kt][1], af[kt][2], af[kt][3], b0, b1);
                mma16816(acc[2 * np + 1][0], acc[2 * np + 1][1],
                         acc[2 * np + 1][2], acc[2 * np + 1][3],
                         af[kt][0], af[kt][1], af[kt][2], af[kt][3], b2, b3);
            }
        };

        auto epi = [&](int nt) {
            float e0 = ex2f(acc[nt][0]);
            float e1 = ex2f(acc[nt][1]);
            float e2 = ex2f(acc[nt][2]);
            float e3 = ex2f(acc[nt][3]);
            unsigned short pr = *(const unsigned short*)&LJ[nt * 8 + 2 * t];
            unsigned lj0 = pr & 0xFFu, lj1 = pr >> 8;
            ra0 += e0 + e1;
            ra1 += e2 + e3;
            if (lj0 == lr0) rp0 += e0;
            if (lj1 == lr0) rp0 += e1;
            if (lj0 == lr1) rp1 += e2;
            if (lj1 == lr1) rp1 += e3;
            if (off != 0) {                  // column sums for block J
                float ca0 = e0 + e2, ca1 = e1 + e3;
                float cp0 = (lj0 == lr0 ? e0 : 0.f) + (lj0 == lr1 ? e2 : 0.f);
                float cp1 = (lj1 == lr0 ? e1 : 0.f) + (lj1 == lr1 ? e3 : 0.f);
#pragma unroll
                for (int s2 = 4; s2 <= 16; s2 <<= 1) {
                    ca0 += __shfl_xor_sync(0xffffffffu, ca0, s2);
                    ca1 += __shfl_xor_sync(0xffffffffu, ca1, s2);
                    cp0 += __shfl_xor_sync(0xffffffffu, cp0, s2);
                    cp1 += __shfl_xor_sync(0xffffffffu, cp1, s2);
                }
                if (lane < 4) {              // g==0 lanes, t == lane
                    int j = bj * 128 + nt * 8 + 2 * lane;
                    atomicAdd(&g_all[j],     ca0);
                    atomicAdd(&g_all[j + 1], ca1);
                    atomicAdd(&g_pos[j],     cp0);
                    atomicAdd(&g_pos[j + 1], cp1);
                }
            }
        };

        // phase 1: MMA n-tiles 0..3
#pragma unroll
        for (int np = 0; np < 4; ++np) mma_np(np);
        // phase 2: MMA n-tiles 4..7 interleaved with epilogue of 0..3
#pragma unroll
        for (int np = 4; np < 8; ++np) {
            mma_np(np);
            epi(2 * (np - 4));
            epi(2 * (np - 4) + 1);
        }
        // phase 3: epilogue of n-tiles 4..7
#pragma unroll
        for (int nt = 8; nt < 16; ++nt) epi(nt);

        // row sums: quad reduce + atomic accumulate
#pragma unroll
        for (int o = 1; o <= 2; o <<= 1) {
            ra0 += __shfl_xor_sync(0xffffffffu, ra0, o);
            ra1 += __shfl_xor_sync(0xffffffffu, ra1, o);
            rp0 += __shfl_xor_sync(0xffffffffu, rp0, o);
            rp1 += __shfl_xor_sync(0xffffffffu, rp1, o);
        }
        if (t == 0) {
            atomicAdd(&g_all[rI + g],     ra0);
            atomicAdd(&g_pos[rI + g],     rp0);
            atomicAdd(&g_all[rI + g + 8], ra1);
            atomicAdd(&g_pos[rI + g + 8], rp1);
        }
    }
}

// ------------------------------------------------------------------ K2 ------
__global__ void k_rowloss(int n) {
    int row = blockIdx.x * blockDim.x + threadIdx.x;
    float li = 0.f;
    int v = 0;
    if (row < n) {
        float es  = g_self[row];
        float pos = g_pos[row] - es;
        float all = g_all[row] - es;
        v = (g_cnt[g_lab[row]] > 1) ? 1 : 0;
        if (v) li = logf(all) - logf(pos);
    }
    __shared__ float ssum[256];
    __shared__ int   scnt[256];
    ssum[threadIdx.x] = li;
    scnt[threadIdx.x] = v;
    __syncthreads();
    for (int o = 128; o > 0; o >>= 1) {
        if (threadIdx.x < o) {
            ssum[threadIdx.x] += ssum[threadIdx.x + o];
            scnt[threadIdx.x] += scnt[threadIdx.x + o];
        }
        __syncthreads();
    }
    if (threadIdx.x == 0) {
        g_bsum[blockIdx.x] = ssum[0];
        g_bcnt[blockIdx.x] = scnt[0];
    }
}

// ------------------------------------------------------------------ K3 ------
__global__ void k_final(float* out, int nb) {
    float s = 0.f;
    int c = 0;
    for (int i = threadIdx.x; i < nb; i += 32) {
        s += g_bsum[i];
        c += g_bcnt[i];
    }
#pragma unroll
    for (int o = 16; o > 0; o >>= 1) {
        s += __shfl_xor_sync(0xffffffffu, s, o);
        c += __shfl_xor_sync(0xffffffffu, c, o);
    }
    if (threadIdx.x == 0) out[0] = (c > 0) ? (s / (float)c) : 0.f;
}

// ----------------------------------------------------------------- launch ---
extern "C" void kernel_launch(void* const* d_in, const int* in_sizes, int n_in,
                              void* d_out, int out_size) {
    const float* emb = (const float*)d_in[0];
    const void*  lab = d_in[1];
    int n = in_sizes[1];                       // 16384

    static int smem_set = 0;
    if (!smem_set) {
        cudaFuncSetAttribute(k_main, cudaFuncAttributeMaxDynamicSharedMemorySize,
                             SMEM_TOTAL);
        smem_set = 1;
    }

    k_zero<<<1, 64>>>((const int*)lab);
    k_convert<<<(n + 255) / 256, 256>>>(emb, lab, n);
    k_main<<<GRID_MAIN, 256, SMEM_TOTAL>>>(n);
    int nb2 = (n + 255) / 256;                 // 64
    k_rowloss<<<nb2, 256>>>(n);
    k_final<<<1, 32>>>((float*)d_out, nb2);
}

// round 13
// speedup vs baseline: 2.0672x; 1.0149x over previous
#include <cuda_runtime.h>
#include <cuda_bf16.h>
#include <cstdint>

// ============================================================================
// ContrastiveLoss, N=16384, D=128, T=0.5, labels in [0,64).
// R11: same symmetric block-pair algorithm as R10 (half the HMMA work), but
// the per-pair schedule fully interleaves the ex2/shuffle/atomic epilogue of
// n-tile np-1 between the HMMA groups of n-tile np, so the MIO/MUFU epilogue
// hides in the tensor pipe's issue gaps instead of running exposed (R10
// exposed 8/16 epilogues -> ~2x the tensor floor).
//   K0z: zero histogram + label dtype sniff
//   K0 : fp32->bf16 (A pre-scaled by 2*log2 e), self-dot exp2, zero g_all/g_pos
//   K1 : persistent 152 CTAs over 8256 unordered 128x128 block pairs,
//        double-buffered cp.async, mma.sync bf16, row sums + column sums.
//   K2 : per-row loss (subtract self) + block reduce;  K3: final reduce
// ============================================================================

#define NMAX 16384
#define DIM  128
#define LDSB 136                 // padded bf16 row stride (272 B)
#define EXP_SCALE 2.8853900817779268f   // 2 * log2(e)
#define GRID_MAIN 152
#define ABYTES (128 * LDSB * 2)  // one 128-row bf16 tile buffer = 34816 B
#define SMEM_TOTAL (4 * ABYTES + 256)

__device__ __nv_bfloat16 g_As[NMAX * DIM];   // scaled copy (A operand)
__device__ __nv_bfloat16 g_Bb[NMAX * DIM];   // unscaled copy (B operand)
__device__ unsigned char g_lab[NMAX];
__device__ int           g_cnt[64];
__device__ int           g_is64;
__device__ float         g_self[NMAX];
__device__ float         g_pos[NMAX];
__device__ float         g_all[NMAX];
__device__ float         g_bsum[256];
__device__ int           g_bcnt[256];

// ---------------------------------------------------------------- helpers ---
__device__ __forceinline__ unsigned smem_u32(const void* p) {
    return (unsigned)__cvta_generic_to_shared(p);
}
__device__ __forceinline__ void cp16(unsigned dst, const void* src) {
    asm volatile("cp.async.cg.shared.global [%0], [%1], 16;\n" :: "r"(dst), "l"(src));
}
__device__ __forceinline__ void cp_commit() {
    asm volatile("cp.async.commit_group;\n");
}
template <int N>
__device__ __forceinline__ void cp_wait() {
    asm volatile("cp.async.wait_group %0;\n" :: "n"(N));
}
__device__ __forceinline__ void ldm4(unsigned addr, unsigned& r0, unsigned& r1,
                                     unsigned& r2, unsigned& r3) {
    asm volatile("ldmatrix.sync.aligned.m8n8.x4.shared.b16 {%0,%1,%2,%3}, [%4];\n"
                 : "=r"(r0), "=r"(r1), "=r"(r2), "=r"(r3) : "r"(addr));
}
__device__ __forceinline__ void mma16816(float& c0, float& c1, float& c2, float& c3,
                                         unsigned a0, unsigned a1, unsigned a2, unsigned a3,
                                         unsigned b0, unsigned b1) {
    asm volatile("mma.sync.aligned.m16n8k16.row.col.f32.bf16.bf16.f32 "
                 "{%0,%1,%2,%3},{%4,%5,%6,%7},{%8,%9},{%0,%1,%2,%3};\n"
                 : "+f"(c0), "+f"(c1), "+f"(c2), "+f"(c3)
                 : "r"(a0), "r"(a1), "r"(a2), "r"(a3), "r"(b0), "r"(b1));
}
__device__ __forceinline__ float ex2f(float x) {
    float y;
    asm("ex2.approx.f32 %0, %1;\n" : "=f"(y) : "f"(x));
    return y;
}

// ------------------------------------------------------------------ K0z -----
__global__ void k_zero(const int* __restrict__ labw) {
    if (threadIdx.x == 0) {
        int odd_or = 0;
        for (int i = 0; i < 64; ++i) odd_or |= labw[2 * i + 1];
        g_is64 = (odd_or == 0) ? 1 : 0;
    }
    if (threadIdx.x < 64) g_cnt[threadIdx.x] = 0;
}

// ------------------------------------------------------------------ K0 ------
__global__ void k_convert(const float* __restrict__ emb,
                          const void* __restrict__ lab, int n) {
    int row = blockIdx.x * blockDim.x + threadIdx.x;
    if (row >= n) return;
    const float4* src = (const float4*)(emb + (size_t)row * DIM);
    __nv_bfloat162* dA = (__nv_bfloat162*)(g_As + (size_t)row * DIM);
    __nv_bfloat162* dB = (__nv_bfloat162*)(g_Bb + (size_t)row * DIM);
    float s = 0.f;
#pragma unroll
    for (int i = 0; i < DIM / 4; ++i) {
        float4 v = src[i];
        __nv_bfloat162 a01 = __floats2bfloat162_rn(v.x * EXP_SCALE, v.y * EXP_SCALE);
        __nv_bfloat162 a23 = __floats2bfloat162_rn(v.z * EXP_SCALE, v.w * EXP_SCALE);
        __nv_bfloat162 b01 = __floats2bfloat162_rn(v.x, v.y);
        __nv_bfloat162 b23 = __floats2bfloat162_rn(v.z, v.w);
        dA[2 * i] = a01; dA[2 * i + 1] = a23;
        dB[2 * i] = b01; dB[2 * i + 1] = b23;
        s += __bfloat162float(a01.x) * __bfloat162float(b01.x)
           + __bfloat162float(a01.y) * __bfloat162float(b01.y)
           + __bfloat162float(a23.x) * __bfloat162float(b23.x)
           + __bfloat162float(a23.y) * __bfloat162float(b23.y);
    }
    g_self[row] = ex2f(s);
    g_all[row]  = 0.f;                 // zero atomic accumulators every call
    g_pos[row]  = 0.f;
    int lb = g_is64 ? (int)((const long long*)lab)[row]
                    : ((const int*)lab)[row];
    g_lab[row] = (unsigned char)lb;
    atomicAdd(&g_cnt[lb & 63], 1);
}

// ------------------------------------------------------------------ K1 ------
__global__ __launch_bounds__(256, 1) void k_main(int n) {
    extern __shared__ char smem[];
    // layout: [A buf0][A buf1][B buf0][B buf1][labJ buf0 128B][labJ buf1 128B]

    const int tid  = threadIdx.x;
    const int lane = tid & 31;
    const int wid  = tid >> 5;
    const int g    = lane >> 2;
    const int t    = lane & 3;

    const int nb    = n >> 7;               // 128 blocks of 128 rows
    const int halfP = nb * (nb >> 1);
    const int NP    = nb * (nb + 1) / 2;    // 8256 unordered pairs

    auto decode = [&](int p, int& bi, int& bj, int& off) {
        if (p < halfP) { off = p / nb; bi = p - off * nb; }
        else           { off = nb >> 1; bi = p - halfP; }
        bj = bi + off; if (bj >= nb) bj -= nb;
    };

    auto load_pair = [&](int p, int buf) {
        int bi, bj, off; decode(p, bi, bj, off);
        __nv_bfloat16* A = (__nv_bfloat16*)(smem + (size_t)buf * ABYTES);
        __nv_bfloat16* B = (__nv_bfloat16*)(smem + (size_t)(2 + buf) * ABYTES);
        const __nv_bfloat16* gA = g_As + (size_t)bi * 128 * DIM;
        const __nv_bfloat16* gB = g_Bb + (size_t)bj * 128 * DIM;
#pragma unroll
        for (int k = 0; k < 8; ++k) {
            int s = tid + k * 256;           // 2048 segments of 16 B each array
            int row = s >> 4, seg = s & 15;
            cp16(smem_u32(&A[row * LDSB + seg * 8]), gA + row * DIM + seg * 8);
            cp16(smem_u32(&B[row * LDSB + seg * 8]), gB + row * DIM + seg * 8);
        }
        if (tid < 8)
            cp16(smem_u32(smem + 4 * ABYTES + buf * 128 + tid * 16),
                 g_lab + bj * 128 + tid * 16);
        cp_commit();
    };

    const int brow = (lane & 7) + ((lane >> 4) << 3);
    const int bcol = ((lane >> 3) & 1) * 8;

    int p  = blockIdx.x;
    if (p < NP) load_pair(p, 0);

    int it = 0;
    for (; p < NP; p += GRID_MAIN, ++it) {
        const int buf = it & 1;
        int bi, bj, off; decode(p, bi, bj, off);

        cp_wait<0>();
        __syncthreads();                     // all threads done with buf^1's pair
        if (p + GRID_MAIN < NP) load_pair(p + GRID_MAIN, buf ^ 1);

        __nv_bfloat16* A = (__nv_bfloat16*)(smem + (size_t)buf * ABYTES);
        __nv_bfloat16* B = (__nv_bfloat16*)(smem + (size_t)(2 + buf) * ABYTES);
        unsigned char* LJ = (unsigned char*)(smem + 4 * ABYTES + buf * 128);

        const int rI = bi * 128 + wid * 16;
        const unsigned lr0 = g_lab[rI + g];
        const unsigned lr1 = g_lab[rI + g + 8];

        // A fragments for this pair
        unsigned af[8][4];
        {
            int arow = wid * 16 + (lane & 15);
            int acol = (lane >> 4) * 8;
#pragma unroll
            for (int kt = 0; kt < 8; ++kt)
                ldm4(smem_u32(&A[arow * LDSB + kt * 16 + acol]),
                     af[kt][0], af[kt][1], af[kt][2], af[kt][3]);
        }

        float acc[16][4];
#pragma unroll
        for (int i = 0; i < 16; ++i)
#pragma unroll
            for (int j = 0; j < 4; ++j) acc[i][j] = 0.f;

        float ra0 = 0.f, ra1 = 0.f, rp0 = 0.f, rp1 = 0.f;

        auto mma_np = [&](int np) {
#pragma unroll
            for (int kt = 0; kt < 8; ++kt) {
                unsigned b0, b1, b2, b3;
                ldm4(smem_u32(&B[(np * 16 + brow) * LDSB + kt * 16 + bcol]),
                     b0, b1, b2, b3);
                mma16816(acc[2 * np][0], acc[2 * np][1],
                         acc[2 * np][2], acc[2 * np][3],
                         af[kt][0], af[kt][1], af[kt][2], af[kt][3], b0, b1);
                mma16816(acc[2 * np + 1][0], acc[2 * np + 1][1],
                         acc[2 * np + 1][2], acc[2 * np + 1][3],
                         af[kt][0], af[kt][1], af[kt][2], af[kt][3], b2, b3);
            }
        };

        auto epi = [&](int nt) {
            float e0 = ex2f(acc[nt][0]);
            float e1 = ex2f(acc[nt][1]);
            float e2 = ex2f(acc[nt][2]);
            float e3 = ex2f(acc[nt][3]);
            unsigned short pr = *(const unsigned short*)&LJ[nt * 8 + 2 * t];
            unsigned lj0 = pr & 0xFFu, lj1 = pr >> 8;
            ra0 += e0 + e1;
            ra1 += e2 + e3;
            if (lj0 == lr0) rp0 += e0;
            if (lj1 == lr0) rp0 += e1;
            if (lj0 == lr1) rp1 += e2;
            if (lj1 == lr1) rp1 += e3;
            if (off != 0) {                  // column sums for block J
                float ca0 = e0 + e2, ca1 = e1 + e3;
                float cp0 = (lj0 == lr0 ? e0 : 0.f) + (lj0 == lr1 ? e2 : 0.f);
                float cp1 = (lj1 == lr0 ? e1 : 0.f) + (lj1 == lr1 ? e3 : 0.f);
#pragma unroll
                for (int s2 = 4; s2 <= 16; s2 <<= 1) {
                    ca0 += __shfl_xor_sync(0xffffffffu, ca0, s2);
                    ca1 += __shfl_xor_sync(0xffffffffu, ca1, s2);
                    cp0 += __shfl_xor_sync(0xffffffffu, cp0, s2);
                    cp1 += __shfl_xor_sync(0xffffffffu, cp1, s2);
                }
                if (lane < 4) {              // g==0 lanes, t == lane
                    int j = bj * 128 + nt * 8 + 2 * lane;
                    atomicAdd(&g_all[j],     ca0);
                    atomicAdd(&g_all[j + 1], ca1);
                    atomicAdd(&g_pos[j],     cp0);
                    atomicAdd(&g_pos[j + 1], cp1);
                }
            }
        };

        // fully interleaved schedule: MMA of n-tile np runs with the epilogue
        // of n-tile np-1 in the same basic block -> MIO/MUFU hide under HMMA
        mma_np(0);
#pragma unroll
        for (int np = 1; np < 8; ++np) {
            mma_np(np);
            epi(2 * (np - 1));
            epi(2 * (np - 1) + 1);
        }
        epi(14);
        epi(15);

        // row sums: quad reduce + atomic accumulate
#pragma unroll
        for (int o = 1; o <= 2; o <<= 1) {
            ra0 += __shfl_xor_sync(0xffffffffu, ra0, o);
            ra1 += __shfl_xor_sync(0xffffffffu, ra1, o);
            rp0 += __shfl_xor_sync(0xffffffffu, rp0, o);
            rp1 += __shfl_xor_sync(0xffffffffu, rp1, o);
        }
        if (t == 0) {
            atomicAdd(&g_all[rI + g],     ra0);
            atomicAdd(&g_pos[rI + g],     rp0);
            atomicAdd(&g_all[rI + g + 8], ra1);
            atomicAdd(&g_pos[rI + g + 8], rp1);
        }
    }
}

// ------------------------------------------------------------------ K2 ------
__global__ void k_rowloss(int n) {
    int row = blockIdx.x * blockDim.x + threadIdx.x;
    float li = 0.f;
    int v = 0;
    if (row < n) {
        float es  = g_self[row];
        float pos = g_pos[row] - es;
        float all = g_all[row] - es;
        v = (g_cnt[g_lab[row]] > 1) ? 1 : 0;
        if (v) li = logf(all) - logf(pos);
    }
    __shared__ float ssum[256];
    __shared__ int   scnt[256];
    ssum[threadIdx.x] = li;
    scnt[threadIdx.x] = v;
    __syncthreads();
    for (int o = 128; o > 0; o >>= 1) {
        if (threadIdx.x < o) {
            ssum[threadIdx.x] += ssum[threadIdx.x + o];
            scnt[threadIdx.x] += scnt[threadIdx.x + o];
        }
        __syncthreads();
    }
    if (threadIdx.x == 0) {
        g_bsum[blockIdx.x] = ssum[0];
        g_bcnt[blockIdx.x] = scnt[0];
    }
}

// ------------------------------------------------------------------ K3 ------
__global__ void k_final(float* out, int nb) {
    float s = 0.f;
    int c = 0;
    for (int i = threadIdx.x; i < nb; i += 32) {
        s += g_bsum[i];
        c += g_bcnt[i];
    }
#pragma unroll
    for (int o = 16; o > 0; o >>= 1) {
        s += __shfl_xor_sync(0xffffffffu, s, o);
        c += __shfl_xor_sync(0xffffffffu, c, o);
    }
    if (threadIdx.x == 0) out[0] = (c > 0) ? (s / (float)c) : 0.f;
}

// ----------------------------------------------------------------- launch ---
extern "C" void kernel_launch(void* const* d_in, const int* in_sizes, int n_in,
                              void* d_out, int out_size) {
    const float* emb = (const float*)d_in[0];
    const void*  lab = d_in[1];
    int n = in_sizes[1];                       // 16384

    static int smem_set = 0;
    if (!smem_set) {
        cudaFuncSetAttribute(k_main, cudaFuncAttributeMaxDynamicSharedMemorySize,
                             SMEM_TOTAL);
        smem_set = 1;
    }

    k_zero<<<1, 64>>>((const int*)lab);
    k_convert<<<(n + 255) / 256, 256>>>(emb, lab, n);
    k_main<<<GRID_MAIN, 256, SMEM_TOTAL>>>(n);
    int nb2 = (n + 255) / 256;                 // 64
    k_rowloss<<<nb2, 256>>>(n);
    k_final<<<1, 32>>>((float*)d_out, nb2);
}

// round 14
// speedup vs baseline: 2.1646x; 1.0471x over previous
#include <cuda_runtime.h>
#include <cuda_bf16.h>
#include <cstdint>

// ============================================================================
// ContrastiveLoss, N=16384, D=128, T=0.5, labels in [0,64).
// R14: symmetric block-pair kernel (R11) with the column-sum ATOMG storm
// removed: each warp's per-nt column sums go to a warp-private SMEM slice via
// plain STS (one value per col per warp per pair -> no atomic needed); a
// single end-of-pair pass sums the 8 slices and issues ONE global atomic per
// (col, array). Global atomics per CTA-pair: 2048 -> 288.
//   K0z: zero histogram + label dtype sniff
//   K0 : fp32->bf16 (A pre-scaled by 2*log2 e), self-dot exp2, zero g_all/g_pos
//   K1 : persistent 152 CTAs over 8256 unordered 128x128 block pairs
//   K2 : per-row loss (subtract self) + block reduce;  K3: final reduce
// ============================================================================

#define NMAX 16384
#define DIM  128
#define LDSB 136                 // padded bf16 row stride (272 B)
#define EXP_SCALE 2.8853900817779268f   // 2 * log2(e)
#define GRID_MAIN 152
#define ABYTES (128 * LDSB * 2)  // one 128-row bf16 tile buffer = 34816 B
#define COLOFF (4 * ABYTES + 256)
#define SMEM_TOTAL (COLOFF + 2 * 8 * 128 * 4)   // + sColAll/sColPos slices

__device__ __nv_bfloat16 g_As[NMAX * DIM];   // scaled copy (A operand)
__device__ __nv_bfloat16 g_Bb[NMAX * DIM];   // unscaled copy (B operand)
__device__ unsigned char g_lab[NMAX];
__device__ int           g_cnt[64];
__device__ int           g_is64;
__device__ float         g_self[NMAX];
__device__ float         g_pos[NMAX];
__device__ float         g_all[NMAX];
__device__ float         g_bsum[256];
__device__ int           g_bcnt[256];

// ---------------------------------------------------------------- helpers ---
__device__ __forceinline__ unsigned smem_u32(const void* p) {
    return (unsigned)__cvta_generic_to_shared(p);
}
__device__ __forceinline__ void cp16(unsigned dst, const void* src) {
    asm volatile("cp.async.cg.shared.global [%0], [%1], 16;\n" :: "r"(dst), "l"(src));
}
__device__ __forceinline__ void cp_commit() {
    asm volatile("cp.async.commit_group;\n");
}
template <int N>
__device__ __forceinline__ void cp_wait() {
    asm volatile("cp.async.wait_group %0;\n" :: "n"(N));
}
__device__ __forceinline__ void ldm4(unsigned addr, unsigned& r0, unsigned& r1,
                                     unsigned& r2, unsigned& r3) {
    asm volatile("ldmatrix.sync.aligned.m8n8.x4.shared.b16 {%0,%1,%2,%3}, [%4];\n"
                 : "=r"(r0), "=r"(r1), "=r"(r2), "=r"(r3) : "r"(addr));
}
__device__ __forceinline__ void mma16816(float& c0, float& c1, float& c2, float& c3,
                                         unsigned a0, unsigned a1, unsigned a2, unsigned a3,
                                         unsigned b0, unsigned b1) {
    asm volatile("mma.sync.aligned.m16n8k16.row.col.f32.bf16.bf16.f32 "
                 "{%0,%1,%2,%3},{%4,%5,%6,%7},{%8,%9},{%0,%1,%2,%3};\n"
                 : "+f"(c0), "+f"(c1), "+f"(c2), "+f"(c3)
                 : "r"(a0), "r"(a1), "r"(a2), "r"(a3), "r"(b0), "r"(b1));
}
__device__ __forceinline__ float ex2f(float x) {
    float y;
    asm("ex2.approx.f32 %0, %1;\n" : "=f"(y) : "f"(x));
    return y;
}

// ------------------------------------------------------------------ K0z -----
__global__ void k_zero(const int* __restrict__ labw) {
    if (threadIdx.x == 0) {
        int odd_or = 0;
        for (int i = 0; i < 64; ++i) odd_or |= labw[2 * i + 1];
        g_is64 = (odd_or == 0) ? 1 : 0;
    }
    if (threadIdx.x < 64) g_cnt[threadIdx.x] = 0;
}

// ------------------------------------------------------------------ K0 ------
__global__ void k_convert(const float* __restrict__ emb,
                          const void* __restrict__ lab, int n) {
    int row = blockIdx.x * blockDim.x + threadIdx.x;
    if (row >= n) return;
    const float4* src = (const float4*)(emb + (size_t)row * DIM);
    __nv_bfloat162* dA = (__nv_bfloat162*)(g_As + (size_t)row * DIM);
    __nv_bfloat162* dB = (__nv_bfloat162*)(g_Bb + (size_t)row * DIM);
    float s = 0.f;
#pragma unroll
    for (int i = 0; i < DIM / 4; ++i) {
        float4 v = src[i];
        __nv_bfloat162 a01 = __floats2bfloat162_rn(v.x * EXP_SCALE, v.y * EXP_SCALE);
        __nv_bfloat162 a23 = __floats2bfloat162_rn(v.z * EXP_SCALE, v.w * EXP_SCALE);
        __nv_bfloat162 b01 = __floats2bfloat162_rn(v.x, v.y);
        __nv_bfloat162 b23 = __floats2bfloat162_rn(v.z, v.w);
        dA[2 * i] = a01; dA[2 * i + 1] = a23;
        dB[2 * i] = b01; dB[2 * i + 1] = b23;
        s += __bfloat162float(a01.x) * __bfloat162float(b01.x)
           + __bfloat162float(a01.y) * __bfloat162float(b01.y)
           + __bfloat162float(a23.x) * __bfloat162float(b23.x)
           + __bfloat162float(a23.y) * __bfloat162float(b23.y);
    }
    g_self[row] = ex2f(s);
    g_all[row]  = 0.f;                 // zero atomic accumulators every call
    g_pos[row]  = 0.f;
    int lb = g_is64 ? (int)((const long long*)lab)[row]
                    : ((const int*)lab)[row];
    g_lab[row] = (unsigned char)lb;
    atomicAdd(&g_cnt[lb & 63], 1);
}

// ------------------------------------------------------------------ K1 ------
__global__ __launch_bounds__(256, 1) void k_main(int n) {
    extern __shared__ char smem[];
    // layout: [A buf0][A buf1][B buf0][B buf1][labJ 2x128B][sColAll 8x128][sColPos 8x128]

    const int tid  = threadIdx.x;
    const int lane = tid & 31;
    const int wid  = tid >> 5;
    const int g    = lane >> 2;
    const int t    = lane & 3;

    float* sColAll = (float*)(smem + COLOFF);
    float* sColPos = sColAll + 8 * 128;

    const int nb    = n >> 7;               // 128 blocks of 128 rows
    const int halfP = nb * (nb >> 1);
    const int NP    = nb * (nb + 1) / 2;    // 8256 unordered pairs

    auto decode = [&](int p, int& bi, int& bj, int& off) {
        if (p < halfP) { off = p / nb; bi = p - off * nb; }
        else           { off = nb >> 1; bi = p - halfP; }
        bj = bi + off; if (bj >= nb) bj -= nb;
    };

    auto load_pair = [&](int p, int buf) {
        int bi, bj, off; decode(p, bi, bj, off);
        __nv_bfloat16* A = (__nv_bfloat16*)(smem + (size_t)buf * ABYTES);
        __nv_bfloat16* B = (__nv_bfloat16*)(smem + (size_t)(2 + buf) * ABYTES);
        const __nv_bfloat16* gA = g_As + (size_t)bi * 128 * DIM;
        const __nv_bfloat16* gB = g_Bb + (size_t)bj * 128 * DIM;
#pragma unroll
        for (int k = 0; k < 8; ++k) {
            int s = tid + k * 256;           // 2048 segments of 16 B each array
            int row = s >> 4, seg = s & 15;
            cp16(smem_u32(&A[row * LDSB + seg * 8]), gA + row * DIM + seg * 8);
            cp16(smem_u32(&B[row * LDSB + seg * 8]), gB + row * DIM + seg * 8);
        }
        if (tid < 8)
            cp16(smem_u32(smem + 4 * ABYTES + buf * 128 + tid * 16),
                 g_lab + bj * 128 + tid * 16);
        cp_commit();
    };

    const int brow = (lane & 7) + ((lane >> 4) << 3);
    const int bcol = ((lane >> 3) & 1) * 8;

    int p  = blockIdx.x;
    if (p < NP) load_pair(p, 0);

    int it = 0;
    for (; p < NP; p += GRID_MAIN, ++it) {
        const int buf = it & 1;
        int bi, bj, off; decode(p, bi, bj, off);

        cp_wait<0>();
        __syncthreads();                     // prev pair fully consumed
        if (p + GRID_MAIN < NP) load_pair(p + GRID_MAIN, buf ^ 1);

        __nv_bfloat16* A = (__nv_bfloat16*)(smem + (size_t)buf * ABYTES);
        __nv_bfloat16* B = (__nv_bfloat16*)(smem + (size_t)(2 + buf) * ABYTES);
        unsigned char* LJ = (unsigned char*)(smem + 4 * ABYTES + buf * 128);

        const int rI = bi * 128 + wid * 16;
        const unsigned lr0 = g_lab[rI + g];
        const unsigned lr1 = g_lab[rI + g + 8];

        // A fragments for this pair
        unsigned af[8][4];
        {
            int arow = wid * 16 + (lane & 15);
            int acol = (lane >> 4) * 8;
#pragma unroll
            for (int kt = 0; kt < 8; ++kt)
                ldm4(smem_u32(&A[arow * LDSB + kt * 16 + acol]),
                     af[kt][0], af[kt][1], af[kt][2], af[kt][3]);
        }

        float acc[16][4];
#pragma unroll
        for (int i = 0; i < 16; ++i)
#pragma unroll
            for (int j = 0; j < 4; ++j) acc[i][j] = 0.f;

        float ra0 = 0.f, ra1 = 0.f, rp0 = 0.f, rp1 = 0.f;

        auto mma_np = [&](int np) {
#pragma unroll
            for (int kt = 0; kt < 8; ++kt) {
                unsigned b0, b1, b2, b3;
                ldm4(smem_u32(&B[(np * 16 + brow) * LDSB + kt * 16 + bcol]),
                     b0, b1, b2, b3);
                mma16816(acc[2 * np][0], acc[2 * np][1],
                         acc[2 * np][2], acc[2 * np][3],
                         af[kt][0], af[kt][1], af[kt][2], af[kt][3], b0, b1);
                mma16816(acc[2 * np + 1][0], acc[2 * np + 1][1],
                         acc[2 * np + 1][2], acc[2 * np + 1][3],
                         af[kt][0], af[kt][1], af[kt][2], af[kt][3], b2, b3);
            }
        };

        auto epi = [&](int nt) {
            float e0 = ex2f(acc[nt][0]);
            float e1 = ex2f(acc[nt][1]);
            float e2 = ex2f(acc[nt][2]);
            float e3 = ex2f(acc[nt][3]);
            unsigned short pr = *(const unsigned short*)&LJ[nt * 8 + 2 * t];
            unsigned lj0 = pr & 0xFFu, lj1 = pr >> 8;
            ra0 += e0 + e1;
            ra1 += e2 + e3;
            if (lj0 == lr0) rp0 += e0;
            if (lj1 == lr0) rp0 += e1;
            if (lj0 == lr1) rp1 += e2;
            if (lj1 == lr1) rp1 += e3;
            if (off != 0) {                  // column partials for block J
                float ca0 = e0 + e2, ca1 = e1 + e3;
                float cp0 = (lj0 == lr0 ? e0 : 0.f) + (lj0 == lr1 ? e2 : 0.f);
                float cp1 = (lj1 == lr0 ? e1 : 0.f) + (lj1 == lr1 ? e3 : 0.f);
#pragma unroll
                for (int s2 = 4; s2 <= 16; s2 <<= 1) {
                    ca0 += __shfl_xor_sync(0xffffffffu, ca0, s2);
                    ca1 += __shfl_xor_sync(0xffffffffu, ca1, s2);
                    cp0 += __shfl_xor_sync(0xffffffffu, cp0, s2);
                    cp1 += __shfl_xor_sync(0xffffffffu, cp1, s2);
                }
                if (lane < 4) {              // one value per col per warp: STS
                    int c = nt * 8 + 2 * lane;
                    sColAll[wid * 128 + c]     = ca0;
                    sColAll[wid * 128 + c + 1] = ca1;
                    sColPos[wid * 128 + c]     = cp0;
                    sColPos[wid * 128 + c + 1] = cp1;
                }
            }
        };

        // interleaved schedule (kept from R11)
        mma_np(0);
#pragma unroll
        for (int np = 1; np < 8; ++np) {
            mma_np(np);
            epi(2 * (np - 1));
            epi(2 * (np - 1) + 1);
        }
        epi(14);
        epi(15);

        // row sums: quad reduce + atomic accumulate
#pragma unroll
        for (int o = 1; o <= 2; o <<= 1) {
            ra0 += __shfl_xor_sync(0xffffffffu, ra0, o);
            ra1 += __shfl_xor_sync(0xffffffffu, ra1, o);
            rp0 += __shfl_xor_sync(0xffffffffu, rp0, o);
            rp1 += __shfl_xor_sync(0xffffffffu, rp1, o);
        }
        if (t == 0) {
            atomicAdd(&g_all[rI + g],     ra0);
            atomicAdd(&g_pos[rI + g],     rp0);
            atomicAdd(&g_all[rI + g + 8], ra1);
            atomicAdd(&g_pos[rI + g + 8], rp1);
        }

        // end-of-pair column flush: sum the 8 warp slices, ONE ATOMG each
        if (off != 0) {
            __syncthreads();                 // sCol writes visible to all
            int c = tid & 127;
            float s = 0.f;
            if (tid < 128) {
#pragma unroll
                for (int w = 0; w < 8; ++w) s += sColAll[w * 128 + c];
                atomicAdd(&g_all[bj * 128 + c], s);
            } else {
#pragma unroll
                for (int w = 0; w < 8; ++w) s += sColPos[w * 128 + c];
                atomicAdd(&g_pos[bj * 128 + c], s);
            }
        }
    }
}

// ------------------------------------------------------------------ K2 ------
__global__ void k_rowloss(int n) {
    int row = blockIdx.x * blockDim.x + threadIdx.x;
    float li = 0.f;
    int v = 0;
    if (row < n) {
        float es  = g_self[row];
        float pos = g_pos[row] - es;
        float all = g_all[row] - es;
        v = (g_cnt[g_lab[row]] > 1) ? 1 : 0;
        if (v) li = logf(all) - logf(pos);
    }
    __shared__ float ssum[256];
    __shared__ int   scnt[256];
    ssum[threadIdx.x] = li;
    scnt[threadIdx.x] = v;
    __syncthreads();
    for (int o = 128; o > 0; o >>= 1) {
        if (threadIdx.x < o) {
            ssum[threadIdx.x] += ssum[threadIdx.x + o];
            scnt[threadIdx.x] += scnt[threadIdx.x + o];
        }
        __syncthreads();
    }
    if (threadIdx.x == 0) {
        g_bsum[blockIdx.x] = ssum[0];
        g_bcnt[blockIdx.x] = scnt[0];
    }
}

// ------------------------------------------------------------------ K3 ------
__global__ void k_final(float* out, int nb) {
    float s = 0.f;
    int c = 0;
    for (int i = threadIdx.x; i < nb; i += 32) {
        s += g_bsum[i];
        c += g_bcnt[i];
    }
#pragma unroll
    for (int o = 16; o > 0; o >>= 1) {
        s += __shfl_xor_sync(0xffffffffu, s, o);
        c += __shfl_xor_sync(0xffffffffu, c, o);
    }
    if (threadIdx.x == 0) out[0] = (c > 0) ? (s / (float)c) : 0.f;
}

// ----------------------------------------------------------------- launch ---
extern "C" void kernel_launch(void* const* d_in, const int* in_sizes, int n_in,
                              void* d_out, int out_size) {
    const float* emb = (const float*)d_in[0];
    const void*  lab = d_in[1];
    int n = in_sizes[1];                       // 16384

    static int smem_set = 0;
    if (!smem_set) {
        cudaFuncSetAttribute(k_main, cudaFuncAttributeMaxDynamicSharedMemorySize,
                             SMEM_TOTAL);
        smem_set = 1;
    }

    k_zero<<<1, 64>>>((const int*)lab);
    k_convert<<<(n + 255) / 256, 256>>>(emb, lab, n);
    k_main<<<GRID_MAIN, 256, SMEM_TOTAL>>>(n);
    int nb2 = (n + 255) / 256;                 // 64
    k_rowloss<<<nb2, 256>>>(n);
    k_final<<<1, 32>>>((float*)d_out, nb2);
}

// round 16
// speedup vs baseline: 2.3678x; 1.0939x over previous
#include <cuda_runtime.h>
#include <cuda_bf16.h>
#include <cstdint>

// ============================================================================
// ContrastiveLoss, N=16384, D=128, T=0.5, labels in [0,64).
// R16 = R15 with the epilogue double-count fixed (tail was epi(4..7) after the
// interleave already ran epi(4),epi(5); now epi(6),epi(7) only).
// 32x64 warp tiles (4 M-warps x 2 N-warps): column butterflies cover 32 rows
// -> SHFL ~halved, B LDSM halved vs 16x128. k_main at launch position 3 to
// land in ncu's capture slot.
//   K0z : zero histogram/done + label dtype sniff
//   K0  : fp32->bf16 (A pre-scaled by 2*log2 e), self-dot exp2, zero sums
//   Kd  : dummy (slot alignment)
//   K1  : persistent 152 CTAs over 8256 unordered 128x128 block pairs
//   Kp  : per-row loss + two-stage reduce (threadfence pattern) -> d_out[0]
// ============================================================================

#define NMAX 16384
#define DIM  128
#define LDSB 136                 // padded bf16 row stride (272 B)
#define EXP_SCALE 2.8853900817779268f   // 2 * log2(e)
#define GRID_MAIN 152
#define ABYTES (128 * LDSB * 2)  // one 128-row bf16 tile buffer = 34816 B
#define COLOFF (4 * ABYTES + 256)
// sColAll[4][128], sColPos[4][128], sRowAll[2][128], sRowPos[2][128]
#define SMEM_TOTAL (COLOFF + (4 + 4 + 2 + 2) * 128 * 4)

__device__ __nv_bfloat16 g_As[NMAX * DIM];   // scaled copy (A operand)
__device__ __nv_bfloat16 g_Bb[NMAX * DIM];   // unscaled copy (B operand)
__device__ unsigned char g_lab[NMAX];
__device__ int           g_cnt[64];
__device__ int           g_is64;
__device__ int           g_done;
__device__ float         g_self[NMAX];
__device__ float         g_pos[NMAX];
__device__ float         g_all[NMAX];
__device__ float         g_bsum[256];
__device__ int           g_bcnt[256];

// ---------------------------------------------------------------- helpers ---
__device__ __forceinline__ unsigned smem_u32(const void* p) {
    return (unsigned)__cvta_generic_to_shared(p);
}
__device__ __forceinline__ void cp16(unsigned dst, const void* src) {
    asm volatile("cp.async.cg.shared.global [%0], [%1], 16;\n" :: "r"(dst), "l"(src));
}
__device__ __forceinline__ void cp_commit() {
    asm volatile("cp.async.commit_group;\n");
}
template <int N>
__device__ __forceinline__ void cp_wait() {
    asm volatile("cp.async.wait_group %0;\n" :: "n"(N));
}
__device__ __forceinline__ void ldm4(unsigned addr, unsigned& r0, unsigned& r1,
                                     unsigned& r2, unsigned& r3) {
    asm volatile("ldmatrix.sync.aligned.m8n8.x4.shared.b16 {%0,%1,%2,%3}, [%4];\n"
                 : "=r"(r0), "=r"(r1), "=r"(r2), "=r"(r3) : "r"(addr));
}
__device__ __forceinline__ void mma16816(float& c0, float& c1, float& c2, float& c3,
                                         unsigned a0, unsigned a1, unsigned a2, unsigned a3,
                                         unsigned b0, unsigned b1) {
    asm volatile("mma.sync.aligned.m16n8k16.row.col.f32.bf16.bf16.f32 "
                 "{%0,%1,%2,%3},{%4,%5,%6,%7},{%8,%9},{%0,%1,%2,%3};\n"
                 : "+f"(c0), "+f"(c1), "+f"(c2), "+f"(c3)
                 : "r"(a0), "r"(a1), "r"(a2), "r"(a3), "r"(b0), "r"(b1));
}
__device__ __forceinline__ float ex2f(float x) {
    float y;
    asm("ex2.approx.f32 %0, %1;\n" : "=f"(y) : "f"(x));
    return y;
}

// ------------------------------------------------------------------ K0z -----
__global__ void k_zero(const int* __restrict__ labw) {
    if (threadIdx.x == 0) {
        int odd_or = 0;
        for (int i = 0; i < 64; ++i) odd_or |= labw[2 * i + 1];
        g_is64 = (odd_or == 0) ? 1 : 0;
        g_done = 0;
    }
    if (threadIdx.x < 64) g_cnt[threadIdx.x] = 0;
}

// ------------------------------------------------------------------ K0 ------
__global__ void k_convert(const float* __restrict__ emb,
                          const void* __restrict__ lab, int n) {
    int row = blockIdx.x * blockDim.x + threadIdx.x;
    if (row >= n) return;
    const float4* src = (const float4*)(emb + (size_t)row * DIM);
    __nv_bfloat162* dA = (__nv_bfloat162*)(g_As + (size_t)row * DIM);
    __nv_bfloat162* dB = (__nv_bfloat162*)(g_Bb + (size_t)row * DIM);
    float s = 0.f;
#pragma unroll
    for (int i = 0; i < DIM / 4; ++i) {
        float4 v = src[i];
        __nv_bfloat162 a01 = __floats2bfloat162_rn(v.x * EXP_SCALE, v.y * EXP_SCALE);
        __nv_bfloat162 a23 = __floats2bfloat162_rn(v.z * EXP_SCALE, v.w * EXP_SCALE);
        __nv_bfloat162 b01 = __floats2bfloat162_rn(v.x, v.y);
        __nv_bfloat162 b23 = __floats2bfloat162_rn(v.z, v.w);
        dA[2 * i] = a01; dA[2 * i + 1] = a23;
        dB[2 * i] = b01; dB[2 * i + 1] = b23;
        s += __bfloat162float(a01.x) * __bfloat162float(b01.x)
           + __bfloat162float(a01.y) * __bfloat162float(b01.y)
           + __bfloat162float(a23.x) * __bfloat162float(b23.x)
           + __bfloat162float(a23.y) * __bfloat162float(b23.y);
    }
    g_self[row] = ex2f(s);
    g_all[row]  = 0.f;
    g_pos[row]  = 0.f;
    int lb = g_is64 ? (int)((const long long*)lab)[row]
                    : ((const int*)lab)[row];
    g_lab[row] = (unsigned char)lb;
    atomicAdd(&g_cnt[lb & 63], 1);
}

// ------------------------------------------------------------------ Kd ------
__global__ void k_dummy() {}

// ------------------------------------------------------------------ K1 ------
__global__ __launch_bounds__(256, 1) void k_main(int n) {
    extern __shared__ char smem[];
    // [A buf0][A buf1][B buf0][B buf1][labJ 2x128B][sColAll][sColPos][sRowAll][sRowPos]

    const int tid  = threadIdx.x;
    const int lane = tid & 31;
    const int wid  = tid >> 5;
    const int wm   = wid & 3;            // M strip: rows 32*wm .. +31
    const int wn   = wid >> 2;           // N strip: cols 64*wn .. +63
    const int g    = lane >> 2;
    const int t    = lane & 3;

    float* sColAll = (float*)(smem + COLOFF);          // [4][128]
    float* sColPos = sColAll + 4 * 128;                // [4][128]
    float* sRowAll = sColPos + 4 * 128;                // [2][128]
    float* sRowPos = sRowAll + 2 * 128;                // [2][128]

    const int nb    = n >> 7;
    const int halfP = nb * (nb >> 1);
    const int NP    = nb * (nb + 1) / 2;    // 8256 unordered pairs

    auto decode = [&](int p, int& bi, int& bj, int& off) {
        if (p < halfP) { off = p / nb; bi = p - off * nb; }
        else           { off = nb >> 1; bi = p - halfP; }
        bj = bi + off; if (bj >= nb) bj -= nb;
    };

    auto load_pair = [&](int p, int buf) {
        int bi, bj, off; decode(p, bi, bj, off);
        __nv_bfloat16* A = (__nv_bfloat16*)(smem + (size_t)buf * ABYTES);
        __nv_bfloat16* B = (__nv_bfloat16*)(smem + (size_t)(2 + buf) * ABYTES);
        const __nv_bfloat16* gA = g_As + (size_t)bi * 128 * DIM;
        const __nv_bfloat16* gB = g_Bb + (size_t)bj * 128 * DIM;
#pragma unroll
        for (int k = 0; k < 8; ++k) {
            int s = tid + k * 256;
            int row = s >> 4, seg = s & 15;
            cp16(smem_u32(&A[row * LDSB + seg * 8]), gA + row * DIM + seg * 8);
            cp16(smem_u32(&B[row * LDSB + seg * 8]), gB + row * DIM + seg * 8);
        }
        if (tid < 8)
            cp16(smem_u32(smem + 4 * ABYTES + buf * 128 + tid * 16),
                 g_lab + bj * 128 + tid * 16);
        cp_commit();
    };

    const int brow = (lane & 7) + ((lane >> 4) << 3);
    const int bcol = ((lane >> 3) & 1) * 8;

    int p  = blockIdx.x;
    if (p < NP) load_pair(p, 0);

    int it = 0;
    for (; p < NP; p += GRID_MAIN, ++it) {
        const int buf = it & 1;
        int bi, bj, off; decode(p, bi, bj, off);

        cp_wait<0>();
        __syncthreads();
        if (p + GRID_MAIN < NP) load_pair(p + GRID_MAIN, buf ^ 1);

        __nv_bfloat16* A = (__nv_bfloat16*)(smem + (size_t)buf * ABYTES);
        __nv_bfloat16* B = (__nv_bfloat16*)(smem + (size_t)(2 + buf) * ABYTES);
        unsigned char* LJ = (unsigned char*)(smem + 4 * ABYTES + buf * 128);

        const int rI = bi * 128 + 32 * wm;
        const unsigned lrA = g_lab[rI + g];
        const unsigned lrB = g_lab[rI + 8 + g];
        const unsigned lrC = g_lab[rI + 16 + g];
        const unsigned lrD = g_lab[rI + 24 + g];

        // A fragments: 2 m16 tiles x full K
        unsigned af[2][8][4];
        {
            int arow = lane & 15;
            int acol = (lane >> 4) * 8;
#pragma unroll
            for (int mt = 0; mt < 2; ++mt)
#pragma unroll
                for (int kt = 0; kt < 8; ++kt)
                    ldm4(smem_u32(&A[(32 * wm + 16 * mt + arow) * LDSB + kt * 16 + acol]),
                         af[mt][kt][0], af[mt][kt][1], af[mt][kt][2], af[mt][kt][3]);
        }

        float acc[2][8][4];
#pragma unroll
        for (int m = 0; m < 2; ++m)
#pragma unroll
            for (int i = 0; i < 8; ++i)
#pragma unroll
                for (int j = 0; j < 4; ++j) acc[m][i][j] = 0.f;

        float raA = 0.f, raB = 0.f, raC = 0.f, raD = 0.f;
        float rpA = 0.f, rpB = 0.f, rpC = 0.f, rpD = 0.f;

        auto mma_npg = [&](int npg) {
#pragma unroll
            for (int kt = 0; kt < 8; ++kt) {
                unsigned b0, b1, b2, b3;
                ldm4(smem_u32(&B[(64 * wn + npg * 16 + brow) * LDSB + kt * 16 + bcol]),
                     b0, b1, b2, b3);
                mma16816(acc[0][2 * npg][0], acc[0][2 * npg][1],
                         acc[0][2 * npg][2], acc[0][2 * npg][3],
                         af[0][kt][0], af[0][kt][1], af[0][kt][2], af[0][kt][3], b0, b1);
                mma16816(acc[0][2 * npg + 1][0], acc[0][2 * npg + 1][1],
                         acc[0][2 * npg + 1][2], acc[0][2 * npg + 1][3],
                         af[0][kt][0], af[0][kt][1], af[0][kt][2], af[0][kt][3], b2, b3);
                mma16816(acc[1][2 * npg][0], acc[1][2 * npg][1],
                         acc[1][2 * npg][2], acc[1][2 * npg][3],
                         af[1][kt][0], af[1][kt][1], af[1][kt][2], af[1][kt][3], b0, b1);
                mma16816(acc[1][2 * npg + 1][0], acc[1][2 * npg + 1][1],
                         acc[1][2 * npg + 1][2], acc[1][2 * npg + 1][3],
                         af[1][kt][0], af[1][kt][1], af[1][kt][2], af[1][kt][3], b2, b3);
            }
        };

        auto epi = [&](int nt) {
            float e00 = ex2f(acc[0][nt][0]);
            float e01 = ex2f(acc[0][nt][1]);
            float e02 = ex2f(acc[0][nt][2]);
            float e03 = ex2f(acc[0][nt][3]);
            float e10 = ex2f(acc[1][nt][0]);
            float e11 = ex2f(acc[1][nt][1]);
            float e12 = ex2f(acc[1][nt][2]);
            float e13 = ex2f(acc[1][nt][3]);
            unsigned short pr = *(const unsigned short*)&LJ[64 * wn + nt * 8 + 2 * t];
            unsigned lj0 = pr & 0xFFu, lj1 = pr >> 8;
            raA += e00 + e01; raB += e02 + e03;
            raC += e10 + e11; raD += e12 + e13;
            if (lj0 == lrA) rpA += e00;
            if (lj1 == lrA) rpA += e01;
            if (lj0 == lrB) rpB += e02;
            if (lj1 == lrB) rpB += e03;
            if (lj0 == lrC) rpC += e10;
            if (lj1 == lrC) rpC += e11;
            if (lj0 == lrD) rpD += e12;
            if (lj1 == lrD) rpD += e13;
            if (off != 0) {                  // column partials (32 rows pre-added)
                float ca0 = (e00 + e02) + (e10 + e12);
                float ca1 = (e01 + e03) + (e11 + e13);
                float cp0 = (lj0 == lrA ? e00 : 0.f) + (lj0 == lrB ? e02 : 0.f)
                          + (lj0 == lrC ? e10 : 0.f) + (lj0 == lrD ? e12 : 0.f);
                float cp1 = (lj1 == lrA ? e01 : 0.f) + (lj1 == lrB ? e03 : 0.f)
                          + (lj1 == lrC ? e11 : 0.f) + (lj1 == lrD ? e13 : 0.f);
#pragma unroll
                for (int s2 = 4; s2 <= 16; s2 <<= 1) {
                    ca0 += __shfl_xor_sync(0xffffffffu, ca0, s2);
                    ca1 += __shfl_xor_sync(0xffffffffu, ca1, s2);
                    cp0 += __shfl_xor_sync(0xffffffffu, cp0, s2);
                    cp1 += __shfl_xor_sync(0xffffffffu, cp1, s2);
                }
                if (lane < 4) {              // g==0, lane==t
                    int c = 64 * wn + nt * 8 + 2 * lane;
                    sColAll[wm * 128 + c]     = ca0;
                    sColAll[wm * 128 + c + 1] = ca1;
                    sColPos[wm * 128 + c]     = cp0;
                    sColPos[wm * 128 + c + 1] = cp1;
                }
            }
        };

        // interleaved schedule: mma(npg) with epi of npg-1's two n8 tiles.
        // npg=1..3 emit epi(0..5); tail handles epi(6), epi(7) ONLY (R15 bug:
        // tail re-ran epi(4), epi(5) -> double count).
        mma_npg(0);
#pragma unroll
        for (int npg = 1; npg < 4; ++npg) {
            mma_npg(npg);
            epi(2 * (npg - 1));
            epi(2 * (npg - 1) + 1);
        }
        epi(6); epi(7);

        // row quad-reduce over t, write warp partials (slice = wn)
#pragma unroll
        for (int o = 1; o <= 2; o <<= 1) {
            raA += __shfl_xor_sync(0xffffffffu, raA, o);
            raB += __shfl_xor_sync(0xffffffffu, raB, o);
            raC += __shfl_xor_sync(0xffffffffu, raC, o);
            raD += __shfl_xor_sync(0xffffffffu, raD, o);
            rpA += __shfl_xor_sync(0xffffffffu, rpA, o);
            rpB += __shfl_xor_sync(0xffffffffu, rpB, o);
            rpC += __shfl_xor_sync(0xffffffffu, rpC, o);
            rpD += __shfl_xor_sync(0xffffffffu, rpD, o);
        }
        if (t == 0) {
            int rbse = wn * 128 + 32 * wm + g;
            sRowAll[rbse]      = raA; sRowAll[rbse + 8]  = raB;
            sRowAll[rbse + 16] = raC; sRowAll[rbse + 24] = raD;
            sRowPos[rbse]      = rpA; sRowPos[rbse + 8]  = rpB;
            sRowPos[rbse + 16] = rpC; sRowPos[rbse + 24] = rpD;
        }

        // end-of-pair flush: combine warp slices, one ATOMG per (idx, array)
        __syncthreads();
        if (tid < 128) {
            int c = tid;
            float r = sRowAll[c] + sRowAll[128 + c];
            atomicAdd(&g_all[bi * 128 + c], r);
            if (off != 0) {
                float s = sColAll[c] + sColAll[128 + c]
                        + sColAll[256 + c] + sColAll[384 + c];
                atomicAdd(&g_all[bj * 128 + c], s);
            }
        } else {
            int c = tid - 128;
            float r = sRowPos[c] + sRowPos[128 + c];
            atomicAdd(&g_pos[bi * 128 + c], r);
            if (off != 0) {
                float s = sColPos[c] + sColPos[128 + c]
                        + sColPos[256 + c] + sColPos[384 + c];
                atomicAdd(&g_pos[bj * 128 + c], s);
            }
        }
    }
}

// ------------------------------------------------------------------ Kp ------
__global__ void k_post(float* out, int n) {
    int row = blockIdx.x * blockDim.x + threadIdx.x;
    float li = 0.f;
    int v = 0;
    if (row < n) {
        float es  = g_self[row];
        float pos = g_pos[row] - es;
        float all = g_all[row] - es;
        v = (g_cnt[g_lab[row]] > 1) ? 1 : 0;
        if (v) li = logf(all) - logf(pos);
    }
    __shared__ float ssum[256];
    __shared__ int   scnt[256];
    __shared__ int   slast;
    ssum[threadIdx.x] = li;
    scnt[threadIdx.x] = v;
    __syncthreads();
    for (int o = 128; o > 0; o >>= 1) {
        if (threadIdx.x < o) {
            ssum[threadIdx.x] += ssum[threadIdx.x + o];
            scnt[threadIdx.x] += scnt[threadIdx.x + o];
        }
        __syncthreads();
    }
    if (threadIdx.x == 0) {
        g_bsum[blockIdx.x] = ssum[0];
        g_bcnt[blockIdx.x] = scnt[0];
        __threadfence();
        int d = atomicAdd(&g_done, 1);
        slast = (d == (int)gridDim.x - 1) ? 1 : 0;
    }
    __syncthreads();
    if (slast && threadIdx.x < 32) {
        __threadfence();                     // acquire: order g_bsum reads
        float s = 0.f;
        int c = 0;
        for (int i = threadIdx.x; i < (int)gridDim.x; i += 32) {
            s += g_bsum[i];
            c += g_bcnt[i];
        }
#pragma unroll
        for (int o = 16; o > 0; o >>= 1) {
            s += __shfl_xor_sync(0xffffffffu, s, o);
            c += __shfl_xor_sync(0xffffffffu, c, o);
        }
        if (threadIdx.x == 0) {
            out[0] = (c > 0) ? (s / (float)c) : 0.f;
            g_done = 0;
        }
    }
}

// ----------------------------------------------------------------- launch ---
extern "C" void kernel_launch(void* const* d_in, const int* in_sizes, int n_in,
                              void* d_out, int out_size) {
    const float* emb = (const float*)d_in[0];
    const void*  lab = d_in[1];
    int n = in_sizes[1];                       // 16384

    static int smem_set = 0;
    if (!smem_set) {
        cudaFuncSetAttribute(k_main, cudaFuncAttributeMaxDynamicSharedMemorySize,
                             SMEM_TOTAL);
        smem_set = 1;
    }

    k_zero<<<1, 64>>>((const int*)lab);                 // pos 0
    k_convert<<<(n + 255) / 256, 256>>>(emb, lab, n);   // pos 1
    k_dummy<<<1, 32>>>();                               // pos 2
    k_main<<<GRID_MAIN, 256, SMEM_TOTAL>>>(n);          // pos 3  <- ncu slot
    k_post<<<(n + 255) / 256, 256>>>((float*)d_out, n); // pos 4
}